// round 11
// baseline (speedup 1.0000x reference)
#include <cuda_runtime.h>
#include <cuda_bf16.h>
#include <cuda_fp8.h>
#include <math.h>
#include <stdint.h>

typedef unsigned long long ull;

// ---------------- model dims ----------------
#define NDEPTH 6
#define DMODEL 1024
#define NHEADS 16
#define DHEAD  64
#define SEQ    1024
#define BATCH  4
#define MROWS  (BATCH*SEQ)        // 4096
#define FFI    4096               // FF_INNER
#define BH     (BATCH*NHEADS)     // 64

// fp8 correction scales
#define SHI 16.0f                  // 2^4 for hi-in-fp8
#define SLO 512.0f                 // 2^9 for lo-in-fp8
#define SCORR_INV 1.220703125e-4f  // 2^-13 = 1/(SHI*SLO)

// ---------------- scratch (static device memory; no allocs allowed) ----------------
__device__ float g_xbuf [MROWS*DMODEL];
__device__ float g_S    [(size_t)BH*SEQ*SEQ];     // fp32 scores
__device__ float g_proj [MROWS*DMODEL];
__device__ float g_ff1  [(size_t)MROWS*2*FFI];

__device__ __nv_bfloat16 g_ahi[(size_t)MROWS*FFI];       // GEMM A operand (bf16 hi)
__device__ __nv_bfloat16 g_alo[(size_t)MROWS*FFI];       // (lo kept for attention path reuse)
__device__ __nv_bfloat16 g_bhi[(size_t)(2*FFI)*DMODEL];  // weights [N,K] bf16 hi
__device__ __nv_bfloat16 g_blo[(size_t)(2*FFI)*DMODEL];
__device__ __nv_bfloat16 g_qkvhi[(size_t)MROWS*3*DMODEL];
__device__ __nv_bfloat16 g_qkvlo[(size_t)MROWS*3*DMODEL];
__device__ __nv_bfloat16 g_phi[(size_t)BH*SEQ*SEQ];      // probs split
__device__ __nv_bfloat16 g_plo[(size_t)BH*SEQ*SEQ];

// fp8 correction operands: A8 = [Alo*2^9 | Ahi*2^4] along K (2K bytes per row),
//                          B8 = [Bhi*2^4 | Blo*2^9] along K (2K bytes per row)
__device__ unsigned char g_a8[(size_t)MROWS*2*FFI];       // 32 MB (max K=4096)
__device__ unsigned char g_b8[(size_t)(2*FFI)*2*DMODEL];  // 16 MB (max N=8192,K=1024)

// ---------------- helpers ----------------
__device__ __forceinline__ uint32_t smem_u32(const void* p) {
    uint32_t a;
    asm("{ .reg .u64 t; cvta.to.shared.u64 t, %1; cvt.u32.u64 %0, t; }" : "=r"(a) : "l"(p));
    return a;
}
__device__ __forceinline__ void mma16816(float* c, const uint32_t* a, uint32_t b0, uint32_t b1) {
    asm volatile(
        "mma.sync.aligned.m16n8k16.row.col.f32.bf16.bf16.f32 "
        "{%0,%1,%2,%3}, {%4,%5,%6,%7}, {%8,%9}, {%0,%1,%2,%3};"
        : "+f"(c[0]), "+f"(c[1]), "+f"(c[2]), "+f"(c[3])
        : "r"(a[0]), "r"(a[1]), "r"(a[2]), "r"(a[3]), "r"(b0), "r"(b1));
}
__device__ __forceinline__ void mma16832f8(float* c, const uint32_t* a, uint32_t b0, uint32_t b1) {
    asm volatile(
        "mma.sync.aligned.m16n8k32.row.col.f32.e4m3.e4m3.f32 "
        "{%0,%1,%2,%3}, {%4,%5,%6,%7}, {%8,%9}, {%0,%1,%2,%3};"
        : "+f"(c[0]), "+f"(c[1]), "+f"(c[2]), "+f"(c[3])
        : "r"(a[0]), "r"(a[1]), "r"(a[2]), "r"(a[3]), "r"(b0), "r"(b1));
}
#define LDSM_X4(r0, r1, r2, r3, addr) \
    asm volatile("ldmatrix.sync.aligned.m8n8.x4.shared.b16 {%0,%1,%2,%3}, [%4];" \
                 : "=r"(r0), "=r"(r1), "=r"(r2), "=r"(r3) : "r"(addr))
#define LDSM_X4_T(r0, r1, r2, r3, addr) \
    asm volatile("ldmatrix.sync.aligned.m8n8.x4.trans.shared.b16 {%0,%1,%2,%3}, [%4];" \
                 : "=r"(r0), "=r"(r1), "=r"(r2), "=r"(r3) : "r"(addr))
#define CP_ASYNC16(saddr, gptr) \
    asm volatile("cp.async.cg.shared.global [%0], [%1], 16;" :: "r"(saddr), "l"(gptr))
__device__ __forceinline__ uint32_t sw128(uint32_t off) { return off ^ ((off >> 3) & 0x70u); }
__device__ __forceinline__ void split2(float v, __nv_bfloat16& h, __nv_bfloat16& l) {
    h = __float2bfloat16(v);
    l = __float2bfloat16(v - __bfloat162float(h));
}
__device__ __forceinline__ unsigned char to_e4m3(float v) {
    return (unsigned char)__nv_cvt_float_to_fp8(v, __NV_SATFINITE, __NV_E4M3);
}

// ---------------- split-precision tensor-core GEMM ----------------
// Phase 1 (fp8): acc = (Alo*2^9)(Bhi*2^4) + (Ahi*2^4)(Blo*2^9)  [one GEMM over 2K bytes]
// then acc *= 2^-13
// Phase 2 (bf16): acc += Ahi*Bhi
// 128x128 tile, 128B k-chunks, 256 thr (8 warps, 32x64 warptile), 3-stage cp.async,
// 2 CTAs/SM.
#define GBM 128
#define GBN 128
#define GKC 64
#define NSTAGE 3
#define STAGE_BYTES 32768
#define GSMEM (NSTAGE*STAGE_BYTES + 1024)

__global__ void __launch_bounds__(256, 2) gemm_mma_mixed(
    const __nv_bfloat16* __restrict__ Ahi, const unsigned char* __restrict__ A8,
    const __nv_bfloat16* __restrict__ Bhi, const unsigned char* __restrict__ B8,
    float* __restrict__ C, __nv_bfloat16* __restrict__ Chi, __nv_bfloat16* __restrict__ Clo,
    unsigned char* __restrict__ C8,   // optional fp8 operand output (row stride 2N)
    const float* __restrict__ resid, int M, int N, int K)
{
    extern __shared__ char dsm[];
    const int tid = threadIdx.x;
    const int wid = tid >> 5, lane = tid & 31;
    const int bm = blockIdx.y * GBM, bn = blockIdx.x * GBN;
    const int m0 = (wid & 3) * 32;
    const int n0 = (wid >> 2) * 64;

    uint32_t raw = smem_u32(dsm);
    uint32_t base = (raw + 1023u) & ~1023u;

    const int segC = K / GKC;       // fp8 chunks (128B each over 2K bytes) = bf16 chunks
    const int NC = 2 * segC;

    float acc[2][8][4];
#pragma unroll
    for (int i = 0; i < 2; i++)
#pragma unroll
        for (int j = 0; j < 8; j++)
#pragma unroll
            for (int q = 0; q < 4; q++) acc[i][j][q] = 0.f;

    const int lr = tid >> 3, lq = tid & 7;
    const uint32_t lswo = sw128((uint32_t)(lr * 128 + lq * 16));

    auto issue = [&](int c) {
        uint32_t abase = base + (uint32_t)(c % NSTAGE) * STAGE_BYTES;
        uint32_t bbase = abase + 16384u;
        if (c < segC) {
            const unsigned char* ag = A8 + (size_t)(bm + lr) * (2 * K) + c * 128 + lq * 16;
            const unsigned char* bg = B8 + (size_t)(bn + lr) * (2 * K) + c * 128 + lq * 16;
#pragma unroll
            for (int i = 0; i < 4; i++) {
                CP_ASYNC16(abase + lswo + i * 4096u, ag + (size_t)(i * 32) * (2 * K));
                CP_ASYNC16(bbase + lswo + i * 4096u, bg + (size_t)(i * 32) * (2 * K));
            }
        } else {
            int kc = (c - segC) * GKC;
            const __nv_bfloat16* ag = Ahi + (size_t)(bm + lr) * K + kc + lq * 8;
            const __nv_bfloat16* bg = Bhi + (size_t)(bn + lr) * K + kc + lq * 8;
#pragma unroll
            for (int i = 0; i < 4; i++) {
                CP_ASYNC16(abase + lswo + i * 4096u, ag + (size_t)(i * 32) * K);
                CP_ASYNC16(bbase + lswo + i * 4096u, bg + (size_t)(i * 32) * K);
            }
        }
        asm volatile("cp.async.commit_group;" ::: "memory");
    };

    issue(0);
    issue(1);

    for (int c = 0; c < NC; c++) {
        if (c + 1 < NC) asm volatile("cp.async.wait_group 1;" ::: "memory");
        else            asm volatile("cp.async.wait_group 0;" ::: "memory");
        __syncthreads();
        if (c + 2 < NC) issue(c + 2);

        if (c == segC) {   // fp8 correction phase done: rescale
#pragma unroll
            for (int i = 0; i < 2; i++)
#pragma unroll
                for (int j = 0; j < 8; j++)
#pragma unroll
                    for (int q = 0; q < 4; q++) acc[i][j][q] *= SCORR_INV;
        }

        uint32_t abase = base + (uint32_t)(c % NSTAGE) * STAGE_BYTES;
        uint32_t bbase = abase + 16384u;
        const bool f8 = (c < segC);
#pragma unroll
        for (int ks = 0; ks < 4; ks++) {
            uint32_t a[2][4];
#pragma unroll
            for (int mt = 0; mt < 2; mt++) {
                int row = m0 + mt * 16 + (lane & 15);
                int kb = ks * 16 + ((lane >> 4) << 3);     // b16-unit col; byte = 2*kb
                uint32_t ad = abase + sw128((uint32_t)(row * 128 + kb * 2));
                LDSM_X4(a[mt][0], a[mt][1], a[mt][2], a[mt][3], ad);
            }
            uint32_t b[4][4];
#pragma unroll
            for (int np = 0; np < 4; np++) {
                int nr = n0 + np * 16 + (lane & 7) + ((lane >> 4) << 3);
                int kb = ks * 16 + (((lane >> 3) & 1) << 3);
                uint32_t ad = bbase + sw128((uint32_t)(nr * 128 + kb * 2));
                LDSM_X4(b[np][0], b[np][1], b[np][2], b[np][3], ad);
            }
            if (f8) {
#pragma unroll
                for (int mt = 0; mt < 2; mt++)
#pragma unroll
                    for (int np = 0; np < 4; np++) {
                        mma16832f8(acc[mt][np * 2 + 0], a[mt], b[np][0], b[np][1]);
                        mma16832f8(acc[mt][np * 2 + 1], a[mt], b[np][2], b[np][3]);
                    }
            } else {
#pragma unroll
                for (int mt = 0; mt < 2; mt++)
#pragma unroll
                    for (int np = 0; np < 4; np++) {
                        mma16816(acc[mt][np * 2 + 0], a[mt], b[np][0], b[np][1]);
                        mma16816(acc[mt][np * 2 + 1], a[mt], b[np][2], b[np][3]);
                    }
            }
        }
    }

    // epilogue
#pragma unroll
    for (int mt = 0; mt < 2; mt++) {
        int row = bm + m0 + mt * 16 + (lane >> 2);
#pragma unroll
        for (int nt = 0; nt < 8; nt++) {
            int col = bn + n0 + nt * 8 + (lane & 3) * 2;
            size_t i0 = (size_t)row * N + col;
            size_t i1 = (size_t)(row + 8) * N + col;
            if (Chi) {
                __nv_bfloat162 h2, l2;
                split2(acc[mt][nt][0], h2.x, l2.x);
                split2(acc[mt][nt][1], h2.y, l2.y);
                *(__nv_bfloat162*)&Chi[i0] = h2;
                *(__nv_bfloat162*)&Clo[i0] = l2;
                split2(acc[mt][nt][2], h2.x, l2.x);
                split2(acc[mt][nt][3], h2.y, l2.y);
                *(__nv_bfloat162*)&Chi[i1] = h2;
                *(__nv_bfloat162*)&Clo[i1] = l2;
            } else if (resid) {
                float2 r0 = *(const float2*)&resid[i0];
                float2 r1 = *(const float2*)&resid[i1];
                *(float2*)&C[i0] = make_float2(acc[mt][nt][0] + r0.x, acc[mt][nt][1] + r0.y);
                *(float2*)&C[i1] = make_float2(acc[mt][nt][2] + r1.x, acc[mt][nt][3] + r1.y);
            } else {
                *(float2*)&C[i0] = make_float2(acc[mt][nt][0], acc[mt][nt][1]);
                *(float2*)&C[i1] = make_float2(acc[mt][nt][2], acc[mt][nt][3]);
            }
        }
    }
}

// ---------------- weights: W[K,N] row-major -> bf16 [N,K] split + fp8 B8 [N,2K] ----------------
__global__ void cvt_wt_t(const float* __restrict__ w, __nv_bfloat16* __restrict__ bhi,
                         __nv_bfloat16* __restrict__ blo, unsigned char* __restrict__ b8,
                         int K, int N)
{
    __shared__ float t[32][33];
    int k0 = blockIdx.y * 32, n0 = blockIdx.x * 32;
    int tx = threadIdx.x, ty = threadIdx.y;  // 32 x 8
    #pragma unroll
    for (int i = 0; i < 32; i += 8)
        t[ty + i][tx] = w[(size_t)(k0 + ty + i) * N + n0 + tx];
    __syncthreads();
    #pragma unroll
    for (int i = 0; i < 32; i += 8) {
        float v = t[tx][ty + i];
        __nv_bfloat16 h, l;
        split2(v, h, l);
        int n = n0 + ty + i, k = k0 + tx;
        size_t o = (size_t)n * K + k;
        bhi[o] = h;
        blo[o] = l;
        size_t o8 = (size_t)n * (2 * K) + k;
        b8[o8]     = to_e4m3(__bfloat162float(h) * SHI);   // Bhi_s : pairs with Alo_s
        b8[o8 + K] = to_e4m3(__bfloat162float(l) * SLO);   // Blo_s : pairs with Ahi_s
    }
}

// ---------------- LayerNorm helpers ----------------
__device__ __forceinline__ void red2(float& s, float& sq, int tid)
{
    __shared__ float sh[64];
    for (int o = 16; o; o >>= 1) { s += __shfl_xor_sync(0xffffffffu, s, o); sq += __shfl_xor_sync(0xffffffffu, sq, o); }
    int wid = tid >> 5, lid = tid & 31;
    if (lid == 0) { sh[wid] = s; sh[wid + 32] = sq; }
    __syncthreads();
    if (wid == 0) {
        float a = (lid < 8) ? sh[lid] : 0.f;
        float b = (lid < 8) ? sh[lid + 32] : 0.f;
        for (int o = 4; o; o >>= 1) { a += __shfl_xor_sync(0xffffffffu, a, o); b += __shfl_xor_sync(0xffffffffu, b, o); }
        if (lid == 0) { sh[0] = a; sh[1] = b; }
    }
    __syncthreads();
    s = sh[0];
    sq = sh[1];
}
__device__ __forceinline__ void ln_stats(const float* x, int D, int tid, float& mean, float& rstd)
{
    float s = 0.f, sq = 0.f;
    for (int c = tid; c < D; c += 256) { float v = x[c]; s += v; sq += v * v; }
    red2(s, sq, tid);
    mean = s / D;
    float var = sq / D - mean * mean;
    rstd = rsqrtf(var + 1e-5f);
}

// fp32 out, optional residual
__global__ void ln_kernel(const float* __restrict__ in, const float* __restrict__ g,
                          const float* __restrict__ res, float* __restrict__ out, int D)
{
    int row = blockIdx.x;
    const float* x = in + (size_t)row * D;
    float mean, rstd;
    ln_stats(x, D, threadIdx.x, mean, rstd);
    float* o = out + (size_t)row * D;
    const float* rr = res ? res + (size_t)row * D : nullptr;
    for (int c = threadIdx.x; c < D; c += 256) {
        float v = (x[c] - mean) * rstd * g[c];
        if (rr) v += rr[c];
        o[c] = v;
    }
}

// LN -> bf16 hi + fp8 A8 (GEMM A operands)
__global__ void ln_split(const float* __restrict__ in, const float* __restrict__ g,
                         __nv_bfloat16* __restrict__ hi, unsigned char* __restrict__ a8, int D)
{
    int row = blockIdx.x;
    const float* x = in + (size_t)row * D;
    float mean, rstd;
    ln_stats(x, D, threadIdx.x, mean, rstd);
    for (int c = threadIdx.x; c < D; c += 256) {
        float v = (x[c] - mean) * rstd * g[c];
        __nv_bfloat16 h, l;
        split2(v, h, l);
        hi[(size_t)row * D + c] = h;
        size_t o8 = (size_t)row * (2 * D) + c;
        a8[o8]     = to_e4m3(__bfloat162float(l) * SLO);   // Alo_s
        a8[o8 + D] = to_e4m3(__bfloat162float(h) * SHI);   // Ahi_s
    }
}

// fused GEGLU + LayerNorm -> bf16 hi + fp8 A8
__global__ void geglu_ln_split(const float* __restrict__ ff1, const float* __restrict__ g,
                               __nv_bfloat16* __restrict__ hi, unsigned char* __restrict__ a8)
{
    int row = blockIdx.x;
    int tid = threadIdx.x;
    const float* arow = ff1 + (size_t)row * (2 * FFI);
    float val[FFI / 256];
    float s = 0.f, sq = 0.f;
#pragma unroll
    for (int k = 0; k < FFI / 256; k++) {
        int c = tid + k * 256;
        float a = arow[c];
        float gg = arow[FFI + c];
        float ge = 0.5f * gg * (1.0f + erff(gg * 0.70710678118654752f));
        float v = a * ge;
        val[k] = v;
        s += v;
        sq += v * v;
    }
    red2(s, sq, tid);
    float mean = s / FFI;
    float rstd = rsqrtf(sq / FFI - mean * mean + 1e-5f);
#pragma unroll
    for (int k = 0; k < FFI / 256; k++) {
        int c = tid + k * 256;
        float v = (val[k] - mean) * rstd * g[c];
        __nv_bfloat16 h, l;
        split2(v, h, l);
        hi[(size_t)row * FFI + c] = h;
        size_t o8 = (size_t)row * (2 * FFI) + c;
        a8[o8]       = to_e4m3(__bfloat162float(l) * SLO);
        a8[o8 + FFI] = to_e4m3(__bfloat162float(h) * SHI);
    }
}

// ---------------- tensorized QK^T: S = 0.125 * Q K^T, 64x64 tiles, split-bf16 ----------------
__global__ void __launch_bounds__(128) qk_mma(
    const __nv_bfloat16* __restrict__ qkvhi, const __nv_bfloat16* __restrict__ qkvlo,
    float* __restrict__ S)
{
    int bh = blockIdx.z; int b = bh >> 4, h = bh & 15;
    int jt = blockIdx.x, it = blockIdx.y;
    if (jt > it) return;

    __shared__ char sm[32768];   // Qhi 0, Qlo 8K, Khi 16K, Klo 24K
    uint32_t sb = smem_u32(sm);
    const int tid = threadIdx.x;
    const int wid = tid >> 5, lane = tid & 31;
    const int wm = (wid & 1) * 32, wn = (wid >> 1) * 32;

    const size_t qrow = (size_t)(b * SEQ + it * 64) * (3 * DMODEL) + h * DHEAD;
    const size_t krow = (size_t)(b * SEQ + jt * 64) * (3 * DMODEL) + DMODEL + h * DHEAD;
#pragma unroll
    for (int i = 0; i < 4; i++) {
        int idx = tid + i * 128;
        int r = idx >> 3, q = idx & 7;
        uint32_t swo = sw128((uint32_t)(r * 128 + q * 16));
        size_t qo = qrow + (size_t)r * (3 * DMODEL) + q * 8;
        size_t ko = krow + (size_t)r * (3 * DMODEL) + q * 8;
        *(uint4*)(sm + swo)          = *(const uint4*)(qkvhi + qo);
        *(uint4*)(sm + 8192 + swo)   = *(const uint4*)(qkvlo + qo);
        *(uint4*)(sm + 16384 + swo)  = *(const uint4*)(qkvhi + ko);
        *(uint4*)(sm + 24576 + swo)  = *(const uint4*)(qkvlo + ko);
    }
    __syncthreads();

    float acc[2][4][4];
#pragma unroll
    for (int i = 0; i < 2; i++)
#pragma unroll
        for (int j = 0; j < 4; j++)
#pragma unroll
            for (int q = 0; q < 4; q++) acc[i][j][q] = 0.f;

#pragma unroll
    for (int ks = 0; ks < 4; ks++) {
        uint32_t ah[2][4], al[2][4];
#pragma unroll
        for (int mt = 0; mt < 2; mt++) {
            int row = wm + mt * 16 + (lane & 15);
            int kb = ks * 16 + ((lane >> 4) << 3);
            uint32_t swo = sw128((uint32_t)(row * 128 + kb * 2));
            LDSM_X4(ah[mt][0], ah[mt][1], ah[mt][2], ah[mt][3], sb + swo);
            LDSM_X4(al[mt][0], al[mt][1], al[mt][2], al[mt][3], sb + 8192 + swo);
        }
        uint32_t bfh[2][4], bfl[2][4];
#pragma unroll
        for (int np = 0; np < 2; np++) {
            int nr = wn + np * 16 + (lane & 7) + ((lane >> 4) << 3);
            int kb = ks * 16 + (((lane >> 3) & 1) << 3);
            uint32_t swo = sw128((uint32_t)(nr * 128 + kb * 2));
            LDSM_X4(bfh[np][0], bfh[np][1], bfh[np][2], bfh[np][3], sb + 16384 + swo);
            LDSM_X4(bfl[np][0], bfl[np][1], bfl[np][2], bfl[np][3], sb + 24576 + swo);
        }
#pragma unroll
        for (int mt = 0; mt < 2; mt++)
#pragma unroll
            for (int np = 0; np < 2; np++) {
                mma16816(acc[mt][np * 2 + 0], ah[mt], bfh[np][0], bfh[np][1]);
                mma16816(acc[mt][np * 2 + 0], ah[mt], bfl[np][0], bfl[np][1]);
                mma16816(acc[mt][np * 2 + 0], al[mt], bfh[np][0], bfh[np][1]);
                mma16816(acc[mt][np * 2 + 1], ah[mt], bfh[np][2], bfh[np][3]);
                mma16816(acc[mt][np * 2 + 1], ah[mt], bfl[np][2], bfl[np][3]);
                mma16816(acc[mt][np * 2 + 1], al[mt], bfh[np][2], bfh[np][3]);
            }
    }

    const float scale = 0.125f;
    float* sbase = S + ((size_t)bh << 20);
#pragma unroll
    for (int mt = 0; mt < 2; mt++) {
        int row = it * 64 + wm + mt * 16 + (lane >> 2);
#pragma unroll
        for (int nt = 0; nt < 4; nt++) {
            int col = jt * 64 + wn + nt * 8 + (lane & 3) * 2;
            *(float2*)&sbase[(size_t)row * SEQ + col] =
                make_float2(acc[mt][nt][0] * scale, acc[mt][nt][1] * scale);
            *(float2*)&sbase[(size_t)(row + 8) * SEQ + col] =
                make_float2(acc[mt][nt][2] * scale, acc[mt][nt][3] * scale);
        }
    }
}

// ---------------- row softmax -> split-bf16 P ----------------
__global__ void softmax_split(const float* __restrict__ S,
                              __nv_bfloat16* __restrict__ phi, __nv_bfloat16* __restrict__ plo)
{
    int row = blockIdx.x;            // bh*1024 + i
    int i = row & (SEQ - 1);
    const float* p = S + (size_t)row * SEQ;
    int L = i + 1;
    int tid = threadIdx.x;
    __shared__ float sh[32];

    float val[4];
    int cnt = 0;
    float m = -3.4028235e38f;
    for (int j = tid; j < L; j += 256) { float v = p[j]; val[cnt++] = v; m = fmaxf(m, v); }
    for (int o = 16; o; o >>= 1) m = fmaxf(m, __shfl_xor_sync(0xffffffffu, m, o));
    if ((tid & 31) == 0) sh[tid >> 5] = m;
    __syncthreads();
    if (tid < 32) {
        float v = (tid < 8) ? sh[tid] : -3.4028235e38f;
        for (int o = 4; o; o >>= 1) v = fmaxf(v, __shfl_xor_sync(0xffffffffu, v, o));
        if (tid == 0) sh[0] = v;
    }
    __syncthreads();
    m = sh[0];
    __syncthreads();
    float s = 0.f;
    for (int k = 0; k < cnt; k++) { val[k] = expf(val[k] - m); s += val[k]; }
    for (int o = 16; o; o >>= 1) s += __shfl_xor_sync(0xffffffffu, s, o);
    if ((tid & 31) == 0) sh[tid >> 5] = s;
    __syncthreads();
    if (tid < 32) {
        float v = (tid < 8) ? sh[tid] : 0.f;
        for (int o = 4; o; o >>= 1) v += __shfl_xor_sync(0xffffffffu, v, o);
        if (tid == 0) sh[0] = v;
    }
    __syncthreads();
    float inv = 1.0f / sh[0];
    __nv_bfloat16* ph = phi + (size_t)row * SEQ;
    __nv_bfloat16* pl = plo + (size_t)row * SEQ;
    for (int j = tid, k = 0; j < L; j += 256, k++) {
        float v = val[k] * inv;
        __nv_bfloat16 h, l;
        split2(v, h, l);
        ph[j] = h;
        pl[j] = l;
    }
    int jend = ((i >> 6) + 1) << 6;   // zero-fill diagonal tile remainder
    for (int j = L + tid; j < jend; j += 256) {
        ph[j] = __float2bfloat16(0.f);
        pl[j] = __float2bfloat16(0.f);
    }
}

// ---------------- tensorized P@V: writes bf16 hi + fp8 A8 attn-out ----------------
__global__ void __launch_bounds__(128) pv_mma(
    const __nv_bfloat16* __restrict__ phi, const __nv_bfloat16* __restrict__ plo,
    const __nv_bfloat16* __restrict__ qkvhi, const __nv_bfloat16* __restrict__ qkvlo,
    __nv_bfloat16* __restrict__ ohi, unsigned char* __restrict__ a8)
{
    int it = blockIdx.x;
    int bh = blockIdx.y;
    int b = bh >> 4, h = bh & 15;

    __shared__ char sm[32768];   // Phi 0, Plo 8K, Vhi 16K, Vlo 24K
    uint32_t sb = smem_u32(sm);
    const int tid = threadIdx.x;
    const int wid = tid >> 5, lane = tid & 31;
    const int wm = (wid & 1) * 32, wn = (wid >> 1) * 32;

    float acc[2][4][4];
#pragma unroll
    for (int i = 0; i < 2; i++)
#pragma unroll
        for (int j = 0; j < 4; j++)
#pragma unroll
            for (int q = 0; q < 4; q++) acc[i][j][q] = 0.f;

    const size_t prow = (size_t)(bh * SEQ + it * 64) * SEQ;
    const size_t vrow = 2 * DMODEL + h * DHEAD;
    const int kend = (it + 1) * 64;

    for (int j0 = 0; j0 < kend; j0 += 64) {
#pragma unroll
        for (int i = 0; i < 4; i++) {
            int idx = tid + i * 128;
            int r = idx >> 3, q = idx & 7;
            uint32_t swo = sw128((uint32_t)(r * 128 + q * 16));
            size_t po = prow + (size_t)r * SEQ + j0 + q * 8;
            size_t vo = vrow + (size_t)(b * SEQ + j0 + r) * (3 * DMODEL) + q * 8;
            *(uint4*)(sm + swo)         = *(const uint4*)(phi + po);
            *(uint4*)(sm + 8192 + swo)  = *(const uint4*)(plo + po);
            *(uint4*)(sm + 16384 + swo) = *(const uint4*)(qkvhi + vo);
            *(uint4*)(sm + 24576 + swo) = *(const uint4*)(qkvlo + vo);
        }
        __syncthreads();
#pragma unroll
        for (int ks = 0; ks < 4; ks++) {
            uint32_t ah[2][4], al[2][4];
#pragma unroll
            for (int mt = 0; mt < 2; mt++) {
                int row = wm + mt * 16 + (lane & 15);
                int kb = ks * 16 + ((lane >> 4) << 3);
                uint32_t swo = sw128((uint32_t)(row * 128 + kb * 2));
                LDSM_X4(ah[mt][0], ah[mt][1], ah[mt][2], ah[mt][3], sb + swo);
                LDSM_X4(al[mt][0], al[mt][1], al[mt][2], al[mt][3], sb + 8192 + swo);
            }
            uint32_t bfh[2][4], bfl[2][4];
#pragma unroll
            for (int np = 0; np < 2; np++) {
                int tok = ks * 16 + (lane & 7) + (((lane >> 3) & 1) << 3);
                int dh  = wn + np * 16 + ((lane >> 4) << 3);
                uint32_t swo = sw128((uint32_t)(tok * 128 + dh * 2));
                LDSM_X4_T(bfh[np][0], bfh[np][1], bfh[np][2], bfh[np][3], sb + 16384 + swo);
                LDSM_X4_T(bfl[np][0], bfl[np][1], bfl[np][2], bfl[np][3], sb + 24576 + swo);
            }
#pragma unroll
            for (int mt = 0; mt < 2; mt++)
#pragma unroll
                for (int np = 0; np < 2; np++) {
                    mma16816(acc[mt][np * 2 + 0], ah[mt], bfh[np][0], bfh[np][1]);
                    mma16816(acc[mt][np * 2 + 0], ah[mt], bfl[np][0], bfl[np][1]);
                    mma16816(acc[mt][np * 2 + 0], al[mt], bfh[np][0], bfh[np][1]);
                    mma16816(acc[mt][np * 2 + 1], ah[mt], bfh[np][2], bfh[np][3]);
                    mma16816(acc[mt][np * 2 + 1], ah[mt], bfl[np][2], bfl[np][3]);
                    mma16816(acc[mt][np * 2 + 1], al[mt], bfh[np][2], bfh[np][3]);
                }
        }
        __syncthreads();
    }

    // epilogue: bf16 hi + fp8 operand halves, merged-head layout [MROWS, DMODEL]
#pragma unroll
    for (int mt = 0; mt < 2; mt++) {
        int qrow = it * 64 + wm + mt * 16 + (lane >> 2);
#pragma unroll
        for (int half = 0; half < 2; half++) {
            size_t mrow = (size_t)(b * SEQ + qrow + half * 8);
            size_t bb = mrow * DMODEL + h * DHEAD;
            size_t b8r = mrow * (2 * DMODEL) + h * DHEAD;
#pragma unroll
            for (int nt = 0; nt < 4; nt++) {
                int col = wn + nt * 8 + (lane & 3) * 2;
                float v0 = acc[mt][nt][half * 2 + 0];
                float v1 = acc[mt][nt][half * 2 + 1];
                __nv_bfloat162 h2;
                __nv_bfloat16 l0, l1;
                split2(v0, h2.x, l0);
                split2(v1, h2.y, l1);
                *(__nv_bfloat162*)&ohi[bb + col] = h2;
                a8[b8r + col]     = to_e4m3(__bfloat162float(l0) * SLO);
                a8[b8r + col + 1] = to_e4m3(__bfloat162float(l1) * SLO);
                a8[b8r + DMODEL + col]     = to_e4m3(__bfloat162float(h2.x) * SHI);
                a8[b8r + DMODEL + col + 1] = to_e4m3(__bfloat162float(h2.y) * SHI);
            }
        }
    }
}

// ---------------- orchestration ----------------
extern "C" void kernel_launch(void* const* d_in, const int* in_sizes, int n_in,
                              void* d_out, int out_size)
{
    const float* x_in   = (const float*)d_in[0];
    const float* qkv_w  = (const float*)d_in[1];
    const float* out_w  = (const float*)d_in[2];
    const float* ff_w1  = (const float*)d_in[3];
    const float* ff_w2  = (const float*)d_in[4];
    const float* attn_g = (const float*)d_in[5];
    const float* outln_g= (const float*)d_in[6];
    const float* ffn_g  = (const float*)d_in[7];
    const float* ffln_g = (const float*)d_in[8];
    const float* nin_g  = (const float*)d_in[9];
    const float* nout_g = (const float*)d_in[10];
    float* out = (float*)d_out;

    float *xbuf, *Sb, *proj, *ff1;
    __nv_bfloat16 *ahi, *alo, *bhi, *blo, *qhi, *qlo, *phi, *plo;
    unsigned char *a8, *b8;
    cudaGetSymbolAddress((void**)&xbuf,  g_xbuf);
    cudaGetSymbolAddress((void**)&Sb,    g_S);
    cudaGetSymbolAddress((void**)&proj,  g_proj);
    cudaGetSymbolAddress((void**)&ff1,   g_ff1);
    cudaGetSymbolAddress((void**)&ahi,   g_ahi);
    cudaGetSymbolAddress((void**)&alo,   g_alo);
    cudaGetSymbolAddress((void**)&bhi,   g_bhi);
    cudaGetSymbolAddress((void**)&blo,   g_blo);
    cudaGetSymbolAddress((void**)&qhi,   g_qkvhi);
    cudaGetSymbolAddress((void**)&qlo,   g_qkvlo);
    cudaGetSymbolAddress((void**)&phi,   g_phi);
    cudaGetSymbolAddress((void**)&plo,   g_plo);
    cudaGetSymbolAddress((void**)&a8,    g_a8);
    cudaGetSymbolAddress((void**)&b8,    g_b8);

    cudaFuncSetAttribute(gemm_mma_mixed, cudaFuncAttributeMaxDynamicSharedMemorySize, GSMEM);

    const int M = MROWS;
    ln_kernel<<<M, 256>>>(x_in, nin_g, nullptr, xbuf, DMODEL);

    for (int l = 0; l < NDEPTH; l++) {
        // ---- attention block ----
        ln_split<<<M, 256>>>(xbuf, attn_g + (size_t)l * DMODEL, ahi, a8, DMODEL);
        cvt_wt_t<<<dim3(3 * DMODEL / 32, DMODEL / 32), dim3(32, 8)>>>(
            qkv_w + (size_t)l * DMODEL * 3 * DMODEL, bhi, blo, b8, DMODEL, 3 * DMODEL);
        gemm_mma_mixed<<<dim3(3 * DMODEL / GBN, M / GBM), 256, GSMEM>>>(
            ahi, a8, bhi, b8, nullptr, qhi, qlo, nullptr, nullptr, M, 3 * DMODEL, DMODEL);

        qk_mma<<<dim3(16, 16, BH), 128>>>(qhi, qlo, Sb);
        softmax_split<<<BH * SEQ, 256>>>(Sb, phi, plo);
        pv_mma<<<dim3(16, BH), 128>>>(phi, plo, qhi, qlo, ahi, a8);

        cvt_wt_t<<<dim3(DMODEL / 32, DMODEL / 32), dim3(32, 8)>>>(
            out_w + (size_t)l * DMODEL * DMODEL, bhi, blo, b8, DMODEL, DMODEL);
        gemm_mma_mixed<<<dim3(DMODEL / GBN, M / GBM), 256, GSMEM>>>(
            ahi, a8, bhi, b8, proj, nullptr, nullptr, nullptr, nullptr, M, DMODEL, DMODEL);
        ln_kernel<<<M, 256>>>(proj, outln_g + (size_t)l * DMODEL, xbuf, xbuf, DMODEL);

        // ---- GEGLU feedforward ----
        ln_split<<<M, 256>>>(xbuf, ffn_g + (size_t)l * DMODEL, ahi, a8, DMODEL);
        cvt_wt_t<<<dim3(2 * FFI / 32, DMODEL / 32), dim3(32, 8)>>>(
            ff_w1 + (size_t)l * DMODEL * 2 * FFI, bhi, blo, b8, DMODEL, 2 * FFI);
        gemm_mma_mixed<<<dim3(2 * FFI / GBN, M / GBM), 256, GSMEM>>>(
            ahi, a8, bhi, b8, ff1, nullptr, nullptr, nullptr, nullptr, M, 2 * FFI, DMODEL);
        geglu_ln_split<<<M, 256>>>(ff1, ffln_g + (size_t)l * FFI, ahi, a8);
        cvt_wt_t<<<dim3(DMODEL / 32, FFI / 32), dim3(32, 8)>>>(
            ff_w2 + (size_t)l * FFI * DMODEL, bhi, blo, b8, FFI, DMODEL);
        gemm_mma_mixed<<<dim3(DMODEL / GBN, M / GBM), 256, GSMEM>>>(
            ahi, a8, bhi, b8, xbuf, nullptr, nullptr, nullptr, xbuf, M, DMODEL, FFI);
    }
    ln_kernel<<<M, 256>>>(xbuf, nout_g, nullptr, out, DMODEL);
}

// round 12
// speedup vs baseline: 1.1402x; 1.1402x over previous
#include <cuda_runtime.h>
#include <cuda_bf16.h>
#include <math.h>
#include <stdint.h>

typedef unsigned long long ull;

// ---------------- model dims ----------------
#define NDEPTH 6
#define DMODEL 1024
#define NHEADS 16
#define DHEAD  64
#define SEQ    1024
#define BATCH  4
#define MROWS  (BATCH*SEQ)        // 4096
#define FFI    4096               // FF_INNER
#define BH     (BATCH*NHEADS)     // 64

// ---------------- scratch (static device memory; no allocs allowed) ----------------
__device__ float g_xbuf [MROWS*DMODEL];
__device__ float g_S    [(size_t)BH*SEQ*SEQ];     // fp32 scores
__device__ float g_proj [MROWS*DMODEL];
__device__ float g_ff1  [(size_t)MROWS*2*FFI];

__device__ __nv_bfloat16 g_ahi[(size_t)MROWS*FFI];       // GEMM A operand (split)
__device__ __nv_bfloat16 g_alo[(size_t)MROWS*FFI];
__device__ __nv_bfloat16 g_bhi[(size_t)(2*FFI)*DMODEL];  // weights [N,K] split
__device__ __nv_bfloat16 g_blo[(size_t)(2*FFI)*DMODEL];
__device__ __nv_bfloat16 g_qkvhi[(size_t)MROWS*3*DMODEL];
__device__ __nv_bfloat16 g_qkvlo[(size_t)MROWS*3*DMODEL];
__device__ __nv_bfloat16 g_phi[(size_t)BH*SEQ*SEQ];      // probs split
__device__ __nv_bfloat16 g_plo[(size_t)BH*SEQ*SEQ];

// ---------------- helpers ----------------
__device__ __forceinline__ uint32_t smem_u32(const void* p) {
    uint32_t a;
    asm("{ .reg .u64 t; cvta.to.shared.u64 t, %1; cvt.u32.u64 %0, t; }" : "=r"(a) : "l"(p));
    return a;
}
__device__ __forceinline__ void mma16816(float* c, const uint32_t* a, uint32_t b0, uint32_t b1) {
    asm volatile(
        "mma.sync.aligned.m16n8k16.row.col.f32.bf16.bf16.f32 "
        "{%0,%1,%2,%3}, {%4,%5,%6,%7}, {%8,%9}, {%0,%1,%2,%3};"
        : "+f"(c[0]), "+f"(c[1]), "+f"(c[2]), "+f"(c[3])
        : "r"(a[0]), "r"(a[1]), "r"(a[2]), "r"(a[3]), "r"(b0), "r"(b1));
}
#define LDSM_X4(r0, r1, r2, r3, addr) \
    asm volatile("ldmatrix.sync.aligned.m8n8.x4.shared.b16 {%0,%1,%2,%3}, [%4];" \
                 : "=r"(r0), "=r"(r1), "=r"(r2), "=r"(r3) : "r"(addr))
#define LDSM_X4_T(r0, r1, r2, r3, addr) \
    asm volatile("ldmatrix.sync.aligned.m8n8.x4.trans.shared.b16 {%0,%1,%2,%3}, [%4];" \
                 : "=r"(r0), "=r"(r1), "=r"(r2), "=r"(r3) : "r"(addr))
#define CP_ASYNC16(saddr, gptr) \
    asm volatile("cp.async.cg.shared.global [%0], [%1], 16;" :: "r"(saddr), "l"(gptr))
__device__ __forceinline__ uint32_t sw128(uint32_t off) { return off ^ ((off >> 3) & 0x70u); }
__device__ __forceinline__ void split2(float v, __nv_bfloat16& h, __nv_bfloat16& l) {
    h = __float2bfloat16(v);
    l = __float2bfloat16(v - __bfloat162float(h));
}

// ---------------- split-bf16 tensor-core GEMM ----------------
// C = Ahi*Bhi + Alo*Bhi + Ahi*Blo  (three K-segments, one fp32 accumulator)
// 128x128 tile, BK=64, 256 thr (8 warps, 32x64 warptile), 3-stage cp.async,
// fragment double-buffering across ks steps, 2 CTAs/SM.
#define GBM 128
#define GBN 128
#define GKC 64
#define NSTAGE 3
#define STAGE_BYTES 32768
#define GSMEM (NSTAGE*STAGE_BYTES + 1024)

__global__ void __launch_bounds__(256, 2) gemm_mma_bf16x3(
    const __nv_bfloat16* __restrict__ Ahi, const __nv_bfloat16* __restrict__ Alo,
    const __nv_bfloat16* __restrict__ Bhi, const __nv_bfloat16* __restrict__ Blo,
    float* __restrict__ C, __nv_bfloat16* __restrict__ Chi, __nv_bfloat16* __restrict__ Clo,
    const float* __restrict__ resid, int M, int N, int K)
{
    extern __shared__ char dsm[];
    const int tid = threadIdx.x;
    const int wid = tid >> 5, lane = tid & 31;
    const int bm = blockIdx.y * GBM, bn = blockIdx.x * GBN;
    const int m0 = (wid & 3) * 32;
    const int n0 = (wid >> 2) * 64;

    uint32_t raw = smem_u32(dsm);
    uint32_t base = (raw + 1023u) & ~1023u;

    const int segC = K / GKC;
    const int NC = 3 * segC;

    float acc[2][8][4];
#pragma unroll
    for (int i = 0; i < 2; i++)
#pragma unroll
        for (int j = 0; j < 8; j++)
#pragma unroll
            for (int q = 0; q < 4; q++) acc[i][j][q] = 0.f;

    // per-thread load coords (fixed across chunks)
    const int lr = tid >> 3, lq = tid & 7;
    const uint32_t lswo = sw128((uint32_t)(lr * 128 + lq * 16));

    auto issue = [&](int c) {
        int seg = c / segC;
        int kc = (c - seg * segC) * GKC;
        const __nv_bfloat16* Ag = (seg == 1) ? Alo : Ahi;
        const __nv_bfloat16* Bg = (seg == 2) ? Blo : Bhi;
        uint32_t abase = base + (uint32_t)(c % NSTAGE) * STAGE_BYTES;
        uint32_t bbase = abase + 16384u;
        const __nv_bfloat16* ag = Ag + (size_t)(bm + lr) * K + kc + lq * 8;
        const __nv_bfloat16* bg = Bg + (size_t)(bn + lr) * K + kc + lq * 8;
#pragma unroll
        for (int i = 0; i < 4; i++) {
            CP_ASYNC16(abase + lswo + i * 4096u, ag + (size_t)(i * 32) * K);
            CP_ASYNC16(bbase + lswo + i * 4096u, bg + (size_t)(i * 32) * K);
        }
        asm volatile("cp.async.commit_group;" ::: "memory");
    };

    // precomputed per-thread fragment smem offsets (k-step advances by 32 bytes)
    const int arow = (lane & 15), akb = ((lane >> 4) << 3);
    const int brow = (lane & 7) + ((lane >> 4) << 3), bkb = (((lane >> 3) & 1) << 3);

    issue(0);
    issue(1);

    for (int c = 0; c < NC; c++) {
        if (c + 2 < NC) {
            issue(c + 2);
            asm volatile("cp.async.wait_group 2;" ::: "memory");
        } else if (c + 1 < NC) {
            asm volatile("cp.async.wait_group 1;" ::: "memory");
        } else {
            asm volatile("cp.async.wait_group 0;" ::: "memory");
        }
        __syncthreads();

        uint32_t abase = base + (uint32_t)(c % NSTAGE) * STAGE_BYTES;
        uint32_t bbase = abase + 16384u;

        uint32_t fa[2][2][4];   // [buf][mt][reg]
        uint32_t fb[2][4][4];   // [buf][np][reg]

        // load ks=0 fragments into buf 0
#pragma unroll
        for (int mt = 0; mt < 2; mt++) {
            uint32_t ad = abase + sw128((uint32_t)((m0 + mt * 16 + arow) * 128 + akb * 2));
            LDSM_X4(fa[0][mt][0], fa[0][mt][1], fa[0][mt][2], fa[0][mt][3], ad);
        }
#pragma unroll
        for (int np = 0; np < 4; np++) {
            uint32_t ad = bbase + sw128((uint32_t)((n0 + np * 16 + brow) * 128 + bkb * 2));
            LDSM_X4(fb[0][np][0], fb[0][np][1], fb[0][np][2], fb[0][np][3], ad);
        }

#pragma unroll
        for (int ks = 0; ks < 4; ks++) {
            const int cur = ks & 1, nxt = cur ^ 1;
            if (ks < 3) {
                int kb2 = (ks + 1) * 16;
#pragma unroll
                for (int mt = 0; mt < 2; mt++) {
                    uint32_t ad = abase +
                        sw128((uint32_t)((m0 + mt * 16 + arow) * 128 + (kb2 + akb) * 2));
                    LDSM_X4(fa[nxt][mt][0], fa[nxt][mt][1], fa[nxt][mt][2], fa[nxt][mt][3], ad);
                }
#pragma unroll
                for (int np = 0; np < 4; np++) {
                    uint32_t ad = bbase +
                        sw128((uint32_t)((n0 + np * 16 + brow) * 128 + (kb2 + bkb) * 2));
                    LDSM_X4(fb[nxt][np][0], fb[nxt][np][1], fb[nxt][np][2], fb[nxt][np][3], ad);
                }
            }
#pragma unroll
            for (int mt = 0; mt < 2; mt++)
#pragma unroll
                for (int np = 0; np < 4; np++) {
                    mma16816(acc[mt][np * 2 + 0], fa[cur][mt], fb[cur][np][0], fb[cur][np][1]);
                    mma16816(acc[mt][np * 2 + 1], fa[cur][mt], fb[cur][np][2], fb[cur][np][3]);
                }
        }
        __syncthreads();
    }

    // epilogue
#pragma unroll
    for (int mt = 0; mt < 2; mt++) {
        int row = bm + m0 + mt * 16 + (lane >> 2);
#pragma unroll
        for (int nt = 0; nt < 8; nt++) {
            int col = bn + n0 + nt * 8 + (lane & 3) * 2;
            size_t i0 = (size_t)row * N + col;
            size_t i1 = (size_t)(row + 8) * N + col;
            if (Chi) {
                __nv_bfloat162 h2, l2;
                split2(acc[mt][nt][0], h2.x, l2.x);
                split2(acc[mt][nt][1], h2.y, l2.y);
                *(__nv_bfloat162*)&Chi[i0] = h2;
                *(__nv_bfloat162*)&Clo[i0] = l2;
                split2(acc[mt][nt][2], h2.x, l2.x);
                split2(acc[mt][nt][3], h2.y, l2.y);
                *(__nv_bfloat162*)&Chi[i1] = h2;
                *(__nv_bfloat162*)&Clo[i1] = l2;
            } else if (resid) {
                float2 r0 = *(const float2*)&resid[i0];
                float2 r1 = *(const float2*)&resid[i1];
                *(float2*)&C[i0] = make_float2(acc[mt][nt][0] + r0.x, acc[mt][nt][1] + r0.y);
                *(float2*)&C[i1] = make_float2(acc[mt][nt][2] + r1.x, acc[mt][nt][3] + r1.y);
            } else {
                *(float2*)&C[i0] = make_float2(acc[mt][nt][0], acc[mt][nt][1]);
                *(float2*)&C[i1] = make_float2(acc[mt][nt][2], acc[mt][nt][3]);
            }
        }
    }
}

// ---------------- weights: W[K,N] row-major -> B[N,K] transposed split ----------------
__global__ void cvt_wt_t(const float* __restrict__ w, __nv_bfloat16* __restrict__ bhi,
                         __nv_bfloat16* __restrict__ blo, int K, int N)
{
    __shared__ float t[32][33];
    int k0 = blockIdx.y * 32, n0 = blockIdx.x * 32;
    int tx = threadIdx.x, ty = threadIdx.y;  // 32 x 8
    #pragma unroll
    for (int i = 0; i < 32; i += 8)
        t[ty + i][tx] = w[(size_t)(k0 + ty + i) * N + n0 + tx];
    __syncthreads();
    #pragma unroll
    for (int i = 0; i < 32; i += 8) {
        float v = t[tx][ty + i];
        __nv_bfloat16 h, l;
        split2(v, h, l);
        size_t o = (size_t)(n0 + ty + i) * K + k0 + tx;
        bhi[o] = h;
        blo[o] = l;
    }
}

// ---------------- LayerNorm helpers ----------------
__device__ __forceinline__ void red2(float& s, float& sq, int tid)
{
    __shared__ float sh[64];
    for (int o = 16; o; o >>= 1) { s += __shfl_xor_sync(0xffffffffu, s, o); sq += __shfl_xor_sync(0xffffffffu, sq, o); }
    int wid = tid >> 5, lid = tid & 31;
    if (lid == 0) { sh[wid] = s; sh[wid + 32] = sq; }
    __syncthreads();
    if (wid == 0) {
        float a = (lid < 8) ? sh[lid] : 0.f;
        float b = (lid < 8) ? sh[lid + 32] : 0.f;
        for (int o = 4; o; o >>= 1) { a += __shfl_xor_sync(0xffffffffu, a, o); b += __shfl_xor_sync(0xffffffffu, b, o); }
        if (lid == 0) { sh[0] = a; sh[1] = b; }
    }
    __syncthreads();
    s = sh[0];
    sq = sh[1];
}
__device__ __forceinline__ void ln_stats(const float* x, int D, int tid, float& mean, float& rstd)
{
    float s = 0.f, sq = 0.f;
    for (int c = tid; c < D; c += 256) { float v = x[c]; s += v; sq += v * v; }
    red2(s, sq, tid);
    mean = s / D;
    float var = sq / D - mean * mean;
    rstd = rsqrtf(var + 1e-5f);
}

// fp32 out, optional residual
__global__ void ln_kernel(const float* __restrict__ in, const float* __restrict__ g,
                          const float* __restrict__ res, float* __restrict__ out, int D)
{
    int row = blockIdx.x;
    const float* x = in + (size_t)row * D;
    float mean, rstd;
    ln_stats(x, D, threadIdx.x, mean, rstd);
    float* o = out + (size_t)row * D;
    const float* rr = res ? res + (size_t)row * D : nullptr;
    for (int c = threadIdx.x; c < D; c += 256) {
        float v = (x[c] - mean) * rstd * g[c];
        if (rr) v += rr[c];
        o[c] = v;
    }
}

// split-bf16 out (GEMM A operand)
__global__ void ln_split(const float* __restrict__ in, const float* __restrict__ g,
                         __nv_bfloat16* __restrict__ hi, __nv_bfloat16* __restrict__ lo, int D)
{
    int row = blockIdx.x;
    const float* x = in + (size_t)row * D;
    float mean, rstd;
    ln_stats(x, D, threadIdx.x, mean, rstd);
    for (int c = threadIdx.x; c < D; c += 256) {
        float v = (x[c] - mean) * rstd * g[c];
        __nv_bfloat16 h, l;
        split2(v, h, l);
        hi[(size_t)row * D + c] = h;
        lo[(size_t)row * D + c] = l;
    }
}

// fused GEGLU + LayerNorm -> split-bf16 (one block per row of FFI elements)
__global__ void geglu_ln_split(const float* __restrict__ ff1, const float* __restrict__ g,
                               __nv_bfloat16* __restrict__ hi, __nv_bfloat16* __restrict__ lo)
{
    int row = blockIdx.x;
    int tid = threadIdx.x;
    const float* arow = ff1 + (size_t)row * (2 * FFI);
    float val[FFI / 256];
    float s = 0.f, sq = 0.f;
#pragma unroll
    for (int k = 0; k < FFI / 256; k++) {
        int c = tid + k * 256;
        float a = arow[c];
        float gg = arow[FFI + c];
        float ge = 0.5f * gg * (1.0f + erff(gg * 0.70710678118654752f));
        float v = a * ge;
        val[k] = v;
        s += v;
        sq += v * v;
    }
    red2(s, sq, tid);
    float mean = s / FFI;
    float rstd = rsqrtf(sq / FFI - mean * mean + 1e-5f);
#pragma unroll
    for (int k = 0; k < FFI / 256; k++) {
        int c = tid + k * 256;
        float v = (val[k] - mean) * rstd * g[c];
        __nv_bfloat16 h, l;
        split2(v, h, l);
        hi[(size_t)row * FFI + c] = h;
        lo[(size_t)row * FFI + c] = l;
    }
}

// ---------------- tensorized QK^T: S = 0.125 * Q K^T, 64x64 tiles, split-bf16 ----------------
__global__ void __launch_bounds__(128) qk_mma(
    const __nv_bfloat16* __restrict__ qkvhi, const __nv_bfloat16* __restrict__ qkvlo,
    float* __restrict__ S)
{
    int bh = blockIdx.z; int b = bh >> 4, h = bh & 15;
    int jt = blockIdx.x, it = blockIdx.y;
    if (jt > it) return;

    __shared__ char sm[32768];   // Qhi 0, Qlo 8K, Khi 16K, Klo 24K
    uint32_t sb = smem_u32(sm);
    const int tid = threadIdx.x;
    const int wid = tid >> 5, lane = tid & 31;
    const int wm = (wid & 1) * 32, wn = (wid >> 1) * 32;

    const size_t qrow = (size_t)(b * SEQ + it * 64) * (3 * DMODEL) + h * DHEAD;
    const size_t krow = (size_t)(b * SEQ + jt * 64) * (3 * DMODEL) + DMODEL + h * DHEAD;
#pragma unroll
    for (int i = 0; i < 4; i++) {
        int idx = tid + i * 128;
        int r = idx >> 3, q = idx & 7;
        uint32_t swo = sw128((uint32_t)(r * 128 + q * 16));
        size_t qo = qrow + (size_t)r * (3 * DMODEL) + q * 8;
        size_t ko = krow + (size_t)r * (3 * DMODEL) + q * 8;
        *(uint4*)(sm + swo)          = *(const uint4*)(qkvhi + qo);
        *(uint4*)(sm + 8192 + swo)   = *(const uint4*)(qkvlo + qo);
        *(uint4*)(sm + 16384 + swo)  = *(const uint4*)(qkvhi + ko);
        *(uint4*)(sm + 24576 + swo)  = *(const uint4*)(qkvlo + ko);
    }
    __syncthreads();

    float acc[2][4][4];
#pragma unroll
    for (int i = 0; i < 2; i++)
#pragma unroll
        for (int j = 0; j < 4; j++)
#pragma unroll
            for (int q = 0; q < 4; q++) acc[i][j][q] = 0.f;

#pragma unroll
    for (int ks = 0; ks < 4; ks++) {
        uint32_t ah[2][4], al[2][4];
#pragma unroll
        for (int mt = 0; mt < 2; mt++) {
            int row = wm + mt * 16 + (lane & 15);
            int kb = ks * 16 + ((lane >> 4) << 3);
            uint32_t swo = sw128((uint32_t)(row * 128 + kb * 2));
            LDSM_X4(ah[mt][0], ah[mt][1], ah[mt][2], ah[mt][3], sb + swo);
            LDSM_X4(al[mt][0], al[mt][1], al[mt][2], al[mt][3], sb + 8192 + swo);
        }
        uint32_t bfh[2][4], bfl[2][4];
#pragma unroll
        for (int np = 0; np < 2; np++) {
            int nr = wn + np * 16 + (lane & 7) + ((lane >> 4) << 3);
            int kb = ks * 16 + (((lane >> 3) & 1) << 3);
            uint32_t swo = sw128((uint32_t)(nr * 128 + kb * 2));
            LDSM_X4(bfh[np][0], bfh[np][1], bfh[np][2], bfh[np][3], sb + 16384 + swo);
            LDSM_X4(bfl[np][0], bfl[np][1], bfl[np][2], bfl[np][3], sb + 24576 + swo);
        }
#pragma unroll
        for (int mt = 0; mt < 2; mt++)
#pragma unroll
            for (int np = 0; np < 2; np++) {
                mma16816(acc[mt][np * 2 + 0], ah[mt], bfh[np][0], bfh[np][1]);
                mma16816(acc[mt][np * 2 + 0], ah[mt], bfl[np][0], bfl[np][1]);
                mma16816(acc[mt][np * 2 + 0], al[mt], bfh[np][0], bfh[np][1]);
                mma16816(acc[mt][np * 2 + 1], ah[mt], bfh[np][2], bfh[np][3]);
                mma16816(acc[mt][np * 2 + 1], ah[mt], bfl[np][2], bfl[np][3]);
                mma16816(acc[mt][np * 2 + 1], al[mt], bfh[np][2], bfh[np][3]);
            }
    }

    const float scale = 0.125f;
    float* sbase = S + ((size_t)bh << 20);
#pragma unroll
    for (int mt = 0; mt < 2; mt++) {
        int row = it * 64 + wm + mt * 16 + (lane >> 2);
#pragma unroll
        for (int nt = 0; nt < 4; nt++) {
            int col = jt * 64 + wn + nt * 8 + (lane & 3) * 2;
            *(float2*)&sbase[(size_t)row * SEQ + col] =
                make_float2(acc[mt][nt][0] * scale, acc[mt][nt][1] * scale);
            *(float2*)&sbase[(size_t)(row + 8) * SEQ + col] =
                make_float2(acc[mt][nt][2] * scale, acc[mt][nt][3] * scale);
        }
    }
}

// ---------------- row softmax -> split-bf16 P ----------------
__global__ void softmax_split(const float* __restrict__ S,
                              __nv_bfloat16* __restrict__ phi, __nv_bfloat16* __restrict__ plo)
{
    int row = blockIdx.x;            // bh*1024 + i
    int i = row & (SEQ - 1);
    const float* p = S + (size_t)row * SEQ;
    int L = i + 1;
    int tid = threadIdx.x;
    __shared__ float sh[32];

    float val[4];
    int cnt = 0;
    float m = -3.4028235e38f;
    for (int j = tid; j < L; j += 256) { float v = p[j]; val[cnt++] = v; m = fmaxf(m, v); }
    for (int o = 16; o; o >>= 1) m = fmaxf(m, __shfl_xor_sync(0xffffffffu, m, o));
    if ((tid & 31) == 0) sh[tid >> 5] = m;
    __syncthreads();
    if (tid < 32) {
        float v = (tid < 8) ? sh[tid] : -3.4028235e38f;
        for (int o = 4; o; o >>= 1) v = fmaxf(v, __shfl_xor_sync(0xffffffffu, v, o));
        if (tid == 0) sh[0] = v;
    }
    __syncthreads();
    m = sh[0];
    __syncthreads();
    float s = 0.f;
    for (int k = 0; k < cnt; k++) { val[k] = expf(val[k] - m); s += val[k]; }
    for (int o = 16; o; o >>= 1) s += __shfl_xor_sync(0xffffffffu, s, o);
    if ((tid & 31) == 0) sh[tid >> 5] = s;
    __syncthreads();
    if (tid < 32) {
        float v = (tid < 8) ? sh[tid] : 0.f;
        for (int o = 4; o; o >>= 1) v += __shfl_xor_sync(0xffffffffu, v, o);
        if (tid == 0) sh[0] = v;
    }
    __syncthreads();
    float inv = 1.0f / sh[0];
    __nv_bfloat16* ph = phi + (size_t)row * SEQ;
    __nv_bfloat16* pl = plo + (size_t)row * SEQ;
    for (int j = tid, k = 0; j < L; j += 256, k++) {
        float v = val[k] * inv;
        __nv_bfloat16 h, l;
        split2(v, h, l);
        ph[j] = h;
        pl[j] = l;
    }
    int jend = ((i >> 6) + 1) << 6;   // zero-fill diagonal tile remainder
    for (int j = L + tid; j < jend; j += 256) {
        ph[j] = __float2bfloat16(0.f);
        pl[j] = __float2bfloat16(0.f);
    }
}

// ---------------- tensorized P@V: writes split-bf16 attn-out ----------------
__global__ void __launch_bounds__(128) pv_mma(
    const __nv_bfloat16* __restrict__ phi, const __nv_bfloat16* __restrict__ plo,
    const __nv_bfloat16* __restrict__ qkvhi, const __nv_bfloat16* __restrict__ qkvlo,
    __nv_bfloat16* __restrict__ ohi, __nv_bfloat16* __restrict__ olo)
{
    int it = blockIdx.x;
    int bh = blockIdx.y;
    int b = bh >> 4, h = bh & 15;

    __shared__ char sm[32768];   // Phi 0, Plo 8K, Vhi 16K, Vlo 24K
    uint32_t sb = smem_u32(sm);
    const int tid = threadIdx.x;
    const int wid = tid >> 5, lane = tid & 31;
    const int wm = (wid & 1) * 32, wn = (wid >> 1) * 32;

    float acc[2][4][4];
#pragma unroll
    for (int i = 0; i < 2; i++)
#pragma unroll
        for (int j = 0; j < 4; j++)
#pragma unroll
            for (int q = 0; q < 4; q++) acc[i][j][q] = 0.f;

    const size_t prow = (size_t)(bh * SEQ + it * 64) * SEQ;
    const size_t vrow = 2 * DMODEL + h * DHEAD;
    const int kend = (it + 1) * 64;

    for (int j0 = 0; j0 < kend; j0 += 64) {
#pragma unroll
        for (int i = 0; i < 4; i++) {
            int idx = tid + i * 128;
            int r = idx >> 3, q = idx & 7;
            uint32_t swo = sw128((uint32_t)(r * 128 + q * 16));
            size_t po = prow + (size_t)r * SEQ + j0 + q * 8;
            size_t vo = vrow + (size_t)(b * SEQ + j0 + r) * (3 * DMODEL) + q * 8;
            *(uint4*)(sm + swo)         = *(const uint4*)(phi + po);
            *(uint4*)(sm + 8192 + swo)  = *(const uint4*)(plo + po);
            *(uint4*)(sm + 16384 + swo) = *(const uint4*)(qkvhi + vo);
            *(uint4*)(sm + 24576 + swo) = *(const uint4*)(qkvlo + vo);
        }
        __syncthreads();
#pragma unroll
        for (int ks = 0; ks < 4; ks++) {
            uint32_t ah[2][4], al[2][4];
#pragma unroll
            for (int mt = 0; mt < 2; mt++) {
                int row = wm + mt * 16 + (lane & 15);
                int kb = ks * 16 + ((lane >> 4) << 3);
                uint32_t swo = sw128((uint32_t)(row * 128 + kb * 2));
                LDSM_X4(ah[mt][0], ah[mt][1], ah[mt][2], ah[mt][3], sb + swo);
                LDSM_X4(al[mt][0], al[mt][1], al[mt][2], al[mt][3], sb + 8192 + swo);
            }
            uint32_t bfh[2][4], bfl[2][4];
#pragma unroll
            for (int np = 0; np < 2; np++) {
                int tok = ks * 16 + (lane & 7) + (((lane >> 3) & 1) << 3);
                int dh  = wn + np * 16 + ((lane >> 4) << 3);
                uint32_t swo = sw128((uint32_t)(tok * 128 + dh * 2));
                LDSM_X4_T(bfh[np][0], bfh[np][1], bfh[np][2], bfh[np][3], sb + 16384 + swo);
                LDSM_X4_T(bfl[np][0], bfl[np][1], bfl[np][2], bfl[np][3], sb + 24576 + swo);
            }
#pragma unroll
            for (int mt = 0; mt < 2; mt++)
#pragma unroll
                for (int np = 0; np < 2; np++) {
                    mma16816(acc[mt][np * 2 + 0], ah[mt], bfh[np][0], bfh[np][1]);
                    mma16816(acc[mt][np * 2 + 0], ah[mt], bfl[np][0], bfl[np][1]);
                    mma16816(acc[mt][np * 2 + 0], al[mt], bfh[np][0], bfh[np][1]);
                    mma16816(acc[mt][np * 2 + 1], ah[mt], bfh[np][2], bfh[np][3]);
                    mma16816(acc[mt][np * 2 + 1], ah[mt], bfl[np][2], bfl[np][3]);
                    mma16816(acc[mt][np * 2 + 1], al[mt], bfh[np][2], bfh[np][3]);
                }
        }
        __syncthreads();
    }

    // epilogue: split to bf16 hi/lo attn-out in merged-head layout [MROWS, DMODEL]
#pragma unroll
    for (int mt = 0; mt < 2; mt++) {
        int qrow = it * 64 + wm + mt * 16 + (lane >> 2);
        size_t base0 = (size_t)(b * SEQ + qrow) * DMODEL + h * DHEAD;
        size_t base1 = (size_t)(b * SEQ + qrow + 8) * DMODEL + h * DHEAD;
#pragma unroll
        for (int nt = 0; nt < 4; nt++) {
            int col = wn + nt * 8 + (lane & 3) * 2;
            __nv_bfloat162 h2, l2;
            split2(acc[mt][nt][0], h2.x, l2.x);
            split2(acc[mt][nt][1], h2.y, l2.y);
            *(__nv_bfloat162*)&ohi[base0 + col] = h2;
            *(__nv_bfloat162*)&olo[base0 + col] = l2;
            split2(acc[mt][nt][2], h2.x, l2.x);
            split2(acc[mt][nt][3], h2.y, l2.y);
            *(__nv_bfloat162*)&ohi[base1 + col] = h2;
            *(__nv_bfloat162*)&olo[base1 + col] = l2;
        }
    }
}

// ---------------- orchestration ----------------
extern "C" void kernel_launch(void* const* d_in, const int* in_sizes, int n_in,
                              void* d_out, int out_size)
{
    const float* x_in   = (const float*)d_in[0];
    const float* qkv_w  = (const float*)d_in[1];
    const float* out_w  = (const float*)d_in[2];
    const float* ff_w1  = (const float*)d_in[3];
    const float* ff_w2  = (const float*)d_in[4];
    const float* attn_g = (const float*)d_in[5];
    const float* outln_g= (const float*)d_in[6];
    const float* ffn_g  = (const float*)d_in[7];
    const float* ffln_g = (const float*)d_in[8];
    const float* nin_g  = (const float*)d_in[9];
    const float* nout_g = (const float*)d_in[10];
    float* out = (float*)d_out;

    float *xbuf, *Sb, *proj, *ff1;
    __nv_bfloat16 *ahi, *alo, *bhi, *blo, *qhi, *qlo, *phi, *plo;
    cudaGetSymbolAddress((void**)&xbuf,  g_xbuf);
    cudaGetSymbolAddress((void**)&Sb,    g_S);
    cudaGetSymbolAddress((void**)&proj,  g_proj);
    cudaGetSymbolAddress((void**)&ff1,   g_ff1);
    cudaGetSymbolAddress((void**)&ahi,   g_ahi);
    cudaGetSymbolAddress((void**)&alo,   g_alo);
    cudaGetSymbolAddress((void**)&bhi,   g_bhi);
    cudaGetSymbolAddress((void**)&blo,   g_blo);
    cudaGetSymbolAddress((void**)&qhi,   g_qkvhi);
    cudaGetSymbolAddress((void**)&qlo,   g_qkvlo);
    cudaGetSymbolAddress((void**)&phi,   g_phi);
    cudaGetSymbolAddress((void**)&plo,   g_plo);

    cudaFuncSetAttribute(gemm_mma_bf16x3, cudaFuncAttributeMaxDynamicSharedMemorySize, GSMEM);

    const int M = MROWS;
    ln_kernel<<<M, 256>>>(x_in, nin_g, nullptr, xbuf, DMODEL);

    for (int l = 0; l < NDEPTH; l++) {
        // ---- attention block ----
        ln_split<<<M, 256>>>(xbuf, attn_g + (size_t)l * DMODEL, ahi, alo, DMODEL);
        cvt_wt_t<<<dim3(3 * DMODEL / 32, DMODEL / 32), dim3(32, 8)>>>(
            qkv_w + (size_t)l * DMODEL * 3 * DMODEL, bhi, blo, DMODEL, 3 * DMODEL);
        gemm_mma_bf16x3<<<dim3(3 * DMODEL / GBN, M / GBM), 256, GSMEM>>>(
            ahi, alo, bhi, blo, nullptr, qhi, qlo, nullptr, M, 3 * DMODEL, DMODEL);

        qk_mma<<<dim3(16, 16, BH), 128>>>(qhi, qlo, Sb);
        softmax_split<<<BH * SEQ, 256>>>(Sb, phi, plo);
        pv_mma<<<dim3(16, BH), 128>>>(phi, plo, qhi, qlo, ahi, alo);

        cvt_wt_t<<<dim3(DMODEL / 32, DMODEL / 32), dim3(32, 8)>>>(
            out_w + (size_t)l * DMODEL * DMODEL, bhi, blo, DMODEL, DMODEL);
        gemm_mma_bf16x3<<<dim3(DMODEL / GBN, M / GBM), 256, GSMEM>>>(
            ahi, alo, bhi, blo, proj, nullptr, nullptr, nullptr, M, DMODEL, DMODEL);
        ln_kernel<<<M, 256>>>(proj, outln_g + (size_t)l * DMODEL, xbuf, xbuf, DMODEL);

        // ---- GEGLU feedforward ----
        ln_split<<<M, 256>>>(xbuf, ffn_g + (size_t)l * DMODEL, ahi, alo, DMODEL);
        cvt_wt_t<<<dim3(2 * FFI / 32, DMODEL / 32), dim3(32, 8)>>>(
            ff_w1 + (size_t)l * DMODEL * 2 * FFI, bhi, blo, DMODEL, 2 * FFI);
        gemm_mma_bf16x3<<<dim3(2 * FFI / GBN, M / GBM), 256, GSMEM>>>(
            ahi, alo, bhi, blo, ff1, nullptr, nullptr, nullptr, M, 2 * FFI, DMODEL);
        geglu_ln_split<<<M, 256>>>(ff1, ffln_g + (size_t)l * FFI, ahi, alo);
        cvt_wt_t<<<dim3(DMODEL / 32, FFI / 32), dim3(32, 8)>>>(
            ff_w2 + (size_t)l * FFI * DMODEL, bhi, blo, FFI, DMODEL);
        gemm_mma_bf16x3<<<dim3(DMODEL / GBN, M / GBM), 256, GSMEM>>>(
            ahi, alo, bhi, blo, xbuf, nullptr, nullptr, xbuf, M, DMODEL, FFI);
    }
    ln_kernel<<<M, 256>>>(xbuf, nout_g, nullptr, out, DMODEL);
}

// round 16
// speedup vs baseline: 1.2834x; 1.1255x over previous
#include <cuda_runtime.h>
#include <cuda_bf16.h>
#include <math.h>
#include <stdint.h>

typedef unsigned long long ull;

// ---------------- model dims ----------------
#define NDEPTH 6
#define DMODEL 1024
#define NHEADS 16
#define DHEAD  64
#define SEQ    1024
#define BATCH  4
#define MROWS  (BATCH*SEQ)        // 4096
#define FFI    4096               // FF_INNER
#define BH     (BATCH*NHEADS)     // 64

// ---------------- scratch (static device memory; no allocs allowed) ----------------
__device__ float g_xbuf [MROWS*DMODEL];
__device__ float g_proj [MROWS*DMODEL];
__device__ float g_ff1  [(size_t)MROWS*2*FFI];

__device__ __nv_bfloat16 g_ahi[(size_t)MROWS*FFI];       // GEMM A operand (split)
__device__ __nv_bfloat16 g_alo[(size_t)MROWS*FFI];
__device__ __nv_bfloat16 g_bhi[(size_t)(2*FFI)*DMODEL];  // weights [N,K] split
__device__ __nv_bfloat16 g_blo[(size_t)(2*FFI)*DMODEL];
__device__ __nv_bfloat16 g_qkvhi[(size_t)MROWS*3*DMODEL];
__device__ __nv_bfloat16 g_qkvlo[(size_t)MROWS*3*DMODEL];

// ---------------- helpers ----------------
__device__ __forceinline__ uint32_t smem_u32(const void* p) {
    uint32_t a;
    asm("{ .reg .u64 t; cvta.to.shared.u64 t, %1; cvt.u32.u64 %0, t; }" : "=r"(a) : "l"(p));
    return a;
}
__device__ __forceinline__ void mma16816(float* c, const uint32_t* a, uint32_t b0, uint32_t b1) {
    asm volatile(
        "mma.sync.aligned.m16n8k16.row.col.f32.bf16.bf16.f32 "
        "{%0,%1,%2,%3}, {%4,%5,%6,%7}, {%8,%9}, {%0,%1,%2,%3};"
        : "+f"(c[0]), "+f"(c[1]), "+f"(c[2]), "+f"(c[3])
        : "r"(a[0]), "r"(a[1]), "r"(a[2]), "r"(a[3]), "r"(b0), "r"(b1));
}
#define LDSM_X4(r0, r1, r2, r3, addr) \
    asm volatile("ldmatrix.sync.aligned.m8n8.x4.shared.b16 {%0,%1,%2,%3}, [%4];" \
                 : "=r"(r0), "=r"(r1), "=r"(r2), "=r"(r3) : "r"(addr))
#define LDSM_X4_T(r0, r1, r2, r3, addr) \
    asm volatile("ldmatrix.sync.aligned.m8n8.x4.trans.shared.b16 {%0,%1,%2,%3}, [%4];" \
                 : "=r"(r0), "=r"(r1), "=r"(r2), "=r"(r3) : "r"(addr))
#define CP_ASYNC16(saddr, gptr) \
    asm volatile("cp.async.cg.shared.global [%0], [%1], 16;" :: "r"(saddr), "l"(gptr))
__device__ __forceinline__ uint32_t sw128(uint32_t off) { return off ^ ((off >> 3) & 0x70u); }
__device__ __forceinline__ void split2(float v, __nv_bfloat16& h, __nv_bfloat16& l) {
    h = __float2bfloat16(v);
    l = __float2bfloat16(v - __bfloat162float(h));
}
// fast exp on the FMA pipe (no MUFU). Input clamped so (int) conversion is safe.
__device__ __forceinline__ float fast_exp(float x) {
    x = fmaxf(x, -87.0f);
    float t = x * 1.44269504088896340f;
    float r = rintf(t);
    float f = t - r;
    float p = 1.33335581e-3f;
    p = fmaf(p, f, 9.61812910e-3f);
    p = fmaf(p, f, 5.55041087e-2f);
    p = fmaf(p, f, 2.40226507e-1f);
    p = fmaf(p, f, 6.93147182e-1f);
    p = fmaf(p, f, 1.0f);
    int e = (int)r;
    if (e < -126) e = -126;
    float s = __int_as_float((uint32_t)(e + 127) << 23);
    return p * s;
}

// ---------------- split-bf16 tensor-core GEMM (round-6 proven config) ----------------
#define GBM 128
#define GBN 128
#define GKC 64
#define NSTAGE 3
#define STAGE_BYTES 32768
#define GSMEM (NSTAGE*STAGE_BYTES + 1024)

__global__ void __launch_bounds__(256, 2) gemm_mma_bf16x3(
    const __nv_bfloat16* __restrict__ Ahi, const __nv_bfloat16* __restrict__ Alo,
    const __nv_bfloat16* __restrict__ Bhi, const __nv_bfloat16* __restrict__ Blo,
    float* __restrict__ C, __nv_bfloat16* __restrict__ Chi, __nv_bfloat16* __restrict__ Clo,
    const float* __restrict__ resid, int M, int N, int K)
{
    extern __shared__ char dsm[];
    const int tid = threadIdx.x;
    const int wid = tid >> 5, lane = tid & 31;
    const int bm = blockIdx.y * GBM, bn = blockIdx.x * GBN;
    const int m0 = (wid & 3) * 32;
    const int n0 = (wid >> 2) * 64;

    uint32_t raw = smem_u32(dsm);
    uint32_t base = (raw + 1023u) & ~1023u;

    const int segC = K / GKC;
    const int NC = 3 * segC;

    float acc[2][8][4];
#pragma unroll
    for (int i = 0; i < 2; i++)
#pragma unroll
        for (int j = 0; j < 8; j++)
#pragma unroll
            for (int q = 0; q < 4; q++) acc[i][j][q] = 0.f;

    const int lr = tid >> 3, lq = tid & 7;
    const uint32_t lswo = sw128((uint32_t)(lr * 128 + lq * 16));

    auto issue = [&](int c) {
        int seg = c / segC;
        int kc = (c - seg * segC) * GKC;
        const __nv_bfloat16* Ag = (seg == 1) ? Alo : Ahi;
        const __nv_bfloat16* Bg = (seg == 2) ? Blo : Bhi;
        uint32_t abase = base + (uint32_t)(c % NSTAGE) * STAGE_BYTES;
        uint32_t bbase = abase + 16384u;
        const __nv_bfloat16* ag = Ag + (size_t)(bm + lr) * K + kc + lq * 8;
        const __nv_bfloat16* bg = Bg + (size_t)(bn + lr) * K + kc + lq * 8;
#pragma unroll
        for (int i = 0; i < 4; i++) {
            CP_ASYNC16(abase + lswo + i * 4096u, ag + (size_t)(i * 32) * K);
            CP_ASYNC16(bbase + lswo + i * 4096u, bg + (size_t)(i * 32) * K);
        }
        asm volatile("cp.async.commit_group;" ::: "memory");
    };

    issue(0);
    issue(1);

    for (int c = 0; c < NC; c++) {
        if (c + 2 < NC) {
            issue(c + 2);
            asm volatile("cp.async.wait_group 2;" ::: "memory");
        } else if (c + 1 < NC) {
            asm volatile("cp.async.wait_group 1;" ::: "memory");
        } else {
            asm volatile("cp.async.wait_group 0;" ::: "memory");
        }
        __syncthreads();

        uint32_t abase = base + (uint32_t)(c % NSTAGE) * STAGE_BYTES;
        uint32_t bbase = abase + 16384u;
#pragma unroll
        for (int ks = 0; ks < 4; ks++) {
            uint32_t a[2][4];
#pragma unroll
            for (int mt = 0; mt < 2; mt++) {
                int row = m0 + mt * 16 + (lane & 15);
                int kb = ks * 16 + ((lane >> 4) << 3);
                uint32_t ad = abase + sw128((uint32_t)(row * 128 + kb * 2));
                LDSM_X4(a[mt][0], a[mt][1], a[mt][2], a[mt][3], ad);
            }
            uint32_t b[4][4];
#pragma unroll
            for (int np = 0; np < 4; np++) {
                int nr = n0 + np * 16 + (lane & 7) + ((lane >> 4) << 3);
                int kb = ks * 16 + (((lane >> 3) & 1) << 3);
                uint32_t ad = bbase + sw128((uint32_t)(nr * 128 + kb * 2));
                LDSM_X4(b[np][0], b[np][1], b[np][2], b[np][3], ad);
            }
#pragma unroll
            for (int mt = 0; mt < 2; mt++)
#pragma unroll
                for (int np = 0; np < 4; np++) {
                    mma16816(acc[mt][np * 2 + 0], a[mt], b[np][0], b[np][1]);
                    mma16816(acc[mt][np * 2 + 1], a[mt], b[np][2], b[np][3]);
                }
        }
        __syncthreads();
    }

    // epilogue
#pragma unroll
    for (int mt = 0; mt < 2; mt++) {
        int row = bm + m0 + mt * 16 + (lane >> 2);
#pragma unroll
        for (int nt = 0; nt < 8; nt++) {
            int col = bn + n0 + nt * 8 + (lane & 3) * 2;
            size_t i0 = (size_t)row * N + col;
            size_t i1 = (size_t)(row + 8) * N + col;
            if (Chi) {
                __nv_bfloat162 h2, l2;
                split2(acc[mt][nt][0], h2.x, l2.x);
                split2(acc[mt][nt][1], h2.y, l2.y);
                *(__nv_bfloat162*)&Chi[i0] = h2;
                *(__nv_bfloat162*)&Clo[i0] = l2;
                split2(acc[mt][nt][2], h2.x, l2.x);
                split2(acc[mt][nt][3], h2.y, l2.y);
                *(__nv_bfloat162*)&Chi[i1] = h2;
                *(__nv_bfloat162*)&Clo[i1] = l2;
            } else if (resid) {
                float2 r0 = *(const float2*)&resid[i0];
                float2 r1 = *(const float2*)&resid[i1];
                *(float2*)&C[i0] = make_float2(acc[mt][nt][0] + r0.x, acc[mt][nt][1] + r0.y);
                *(float2*)&C[i1] = make_float2(acc[mt][nt][2] + r1.x, acc[mt][nt][3] + r1.y);
            } else {
                *(float2*)&C[i0] = make_float2(acc[mt][nt][0], acc[mt][nt][1]);
                *(float2*)&C[i1] = make_float2(acc[mt][nt][2], acc[mt][nt][3]);
            }
        }
    }
}

// ---------------- weights: W[K,N] row-major -> B[N,K] transposed split ----------------
__global__ void cvt_wt_t(const float* __restrict__ w, __nv_bfloat16* __restrict__ bhi,
                         __nv_bfloat16* __restrict__ blo, int K, int N)
{
    __shared__ float t[32][33];
    int k0 = blockIdx.y * 32, n0 = blockIdx.x * 32;
    int tx = threadIdx.x, ty = threadIdx.y;  // 32 x 8
    #pragma unroll
    for (int i = 0; i < 32; i += 8)
        t[ty + i][tx] = w[(size_t)(k0 + ty + i) * N + n0 + tx];
    __syncthreads();
    #pragma unroll
    for (int i = 0; i < 32; i += 8) {
        float v = t[tx][ty + i];
        __nv_bfloat16 h, l;
        split2(v, h, l);
        size_t o = (size_t)(n0 + ty + i) * K + k0 + tx;
        bhi[o] = h;
        blo[o] = l;
    }
}

// ---------------- LayerNorm helpers ----------------
__device__ __forceinline__ void red2(float& s, float& sq, int tid)
{
    __shared__ float sh[64];
    for (int o = 16; o; o >>= 1) { s += __shfl_xor_sync(0xffffffffu, s, o); sq += __shfl_xor_sync(0xffffffffu, sq, o); }
    int wid = tid >> 5, lid = tid & 31;
    if (lid == 0) { sh[wid] = s; sh[wid + 32] = sq; }
    __syncthreads();
    if (wid == 0) {
        float a = (lid < 8) ? sh[lid] : 0.f;
        float b = (lid < 8) ? sh[lid + 32] : 0.f;
        for (int o = 4; o; o >>= 1) { a += __shfl_xor_sync(0xffffffffu, a, o); b += __shfl_xor_sync(0xffffffffu, b, o); }
        if (lid == 0) { sh[0] = a; sh[1] = b; }
    }
    __syncthreads();
    s = sh[0];
    sq = sh[1];
}
__device__ __forceinline__ void ln_stats(const float* x, int D, int tid, float& mean, float& rstd)
{
    float s = 0.f, sq = 0.f;
    for (int c = tid; c < D; c += 256) { float v = x[c]; s += v; sq += v * v; }
    red2(s, sq, tid);
    mean = s / D;
    float var = sq / D - mean * mean;
    rstd = rsqrtf(var + 1e-5f);
}

__global__ void ln_kernel(const float* __restrict__ in, const float* __restrict__ g,
                          const float* __restrict__ res, float* __restrict__ out, int D)
{
    int row = blockIdx.x;
    const float* x = in + (size_t)row * D;
    float mean, rstd;
    ln_stats(x, D, threadIdx.x, mean, rstd);
    float* o = out + (size_t)row * D;
    const float* rr = res ? res + (size_t)row * D : nullptr;
    for (int c = threadIdx.x; c < D; c += 256) {
        float v = (x[c] - mean) * rstd * g[c];
        if (rr) v += rr[c];
        o[c] = v;
    }
}

__global__ void ln_split(const float* __restrict__ in, const float* __restrict__ g,
                         __nv_bfloat16* __restrict__ hi, __nv_bfloat16* __restrict__ lo, int D)
{
    int row = blockIdx.x;
    const float* x = in + (size_t)row * D;
    float mean, rstd;
    ln_stats(x, D, threadIdx.x, mean, rstd);
    for (int c = threadIdx.x; c < D; c += 256) {
        float v = (x[c] - mean) * rstd * g[c];
        __nv_bfloat16 h, l;
        split2(v, h, l);
        hi[(size_t)row * D + c] = h;
        lo[(size_t)row * D + c] = l;
    }
}

__global__ void geglu_ln_split(const float* __restrict__ ff1, const float* __restrict__ g,
                               __nv_bfloat16* __restrict__ hi, __nv_bfloat16* __restrict__ lo)
{
    int row = blockIdx.x;
    int tid = threadIdx.x;
    const float* arow = ff1 + (size_t)row * (2 * FFI);
    float val[FFI / 256];
    float s = 0.f, sq = 0.f;
#pragma unroll
    for (int k = 0; k < FFI / 256; k++) {
        int c = tid + k * 256;
        float a = arow[c];
        float gg = arow[FFI + c];
        float ge = 0.5f * gg * (1.0f + erff(gg * 0.70710678118654752f));
        float v = a * ge;
        val[k] = v;
        s += v;
        sq += v * v;
    }
    red2(s, sq, tid);
    float mean = s / FFI;
    float rstd = rsqrtf(sq / FFI - mean * mean + 1e-5f);
#pragma unroll
    for (int k = 0; k < FFI / 256; k++) {
        int c = tid + k * 256;
        float v = (val[k] - mean) * rstd * g[c];
        __nv_bfloat16 h, l;
        split2(v, h, l);
        hi[(size_t)row * FFI + c] = h;
        lo[(size_t)row * FFI + c] = l;
    }
}

// ---------------- fused flash attention ----------------
// One CTA = 64 query rows of one (b,h). 4 warps x 16 rows. Online softmax in
// registers; S/P never touch global memory. Split-bf16 on Q,K and P,V (3-term mma).
// smem: Qhi 0-8K, Qlo 8-16K, Khi 16-24K, Klo 24-32K, Vhi 32-40K, Vlo 40-48K.
__global__ void __launch_bounds__(128) flash_attn(
    const __nv_bfloat16* __restrict__ qkvhi, const __nv_bfloat16* __restrict__ qkvlo,
    __nv_bfloat16* __restrict__ ohi, __nv_bfloat16* __restrict__ olo)
{
    __shared__ char sm[49152];
    uint32_t sb = smem_u32(sm);
    const int it = (int)gridDim.x - 1 - (int)blockIdx.x;   // big tiles first
    const int bh = blockIdx.y;
    const int b = bh >> 4, h = bh & 15;
    const int tid = threadIdx.x;
    const int wid = tid >> 5, lane = tid & 31;

    // ---- load Q tile (64x64 hi/lo) into smem ----
    const size_t qrow = (size_t)(b * SEQ + it * 64) * (3 * DMODEL) + h * DHEAD;
#pragma unroll
    for (int i = 0; i < 4; i++) {
        int idx = tid + i * 128;
        int r = idx >> 3, q = idx & 7;
        uint32_t swo = sw128((uint32_t)(r * 128 + q * 16));
        size_t qo = qrow + (size_t)r * (3 * DMODEL) + q * 8;
        *(uint4*)(sm + swo)        = *(const uint4*)(qkvhi + qo);
        *(uint4*)(sm + 8192 + swo) = *(const uint4*)(qkvlo + qo);
    }
    __syncthreads();

    // ---- Q fragments to registers (warp owns rows wid*16..+15) ----
    uint32_t qh[4][4], ql[4][4];
#pragma unroll
    for (int ks = 0; ks < 4; ks++) {
        int row = wid * 16 + (lane & 15);
        int kb = ks * 16 + ((lane >> 4) << 3);
        uint32_t swo = sw128((uint32_t)(row * 128 + kb * 2));
        LDSM_X4(qh[ks][0], qh[ks][1], qh[ks][2], qh[ks][3], sb + swo);
        LDSM_X4(ql[ks][0], ql[ks][1], ql[ks][2], ql[ks][3], sb + 8192 + swo);
    }

    float oacc[8][4];
#pragma unroll
    for (int j = 0; j < 8; j++)
#pragma unroll
        for (int q = 0; q < 4; q++) oacc[j][q] = 0.f;
    float mrow[2] = {-1e30f, -1e30f};
    float lrow[2] = {0.f, 0.f};

    const size_t kbase = (size_t)b * SEQ * (3 * DMODEL) + DMODEL + h * DHEAD;
    const size_t vbase = (size_t)b * SEQ * (3 * DMODEL) + 2 * DMODEL + h * DHEAD;

    for (int jt = 0; jt <= it; jt++) {
        // ---- load K/V tiles ----
        __syncthreads();
#pragma unroll
        for (int i = 0; i < 4; i++) {
            int idx = tid + i * 128;
            int r = idx >> 3, q = idx & 7;
            uint32_t swo = sw128((uint32_t)(r * 128 + q * 16));
            size_t ko = kbase + (size_t)(jt * 64 + r) * (3 * DMODEL) + q * 8;
            size_t vo = vbase + (size_t)(jt * 64 + r) * (3 * DMODEL) + q * 8;
            *(uint4*)(sm + 16384 + swo) = *(const uint4*)(qkvhi + ko);
            *(uint4*)(sm + 24576 + swo) = *(const uint4*)(qkvlo + ko);
            *(uint4*)(sm + 32768 + swo) = *(const uint4*)(qkvhi + vo);
            *(uint4*)(sm + 40960 + swo) = *(const uint4*)(qkvlo + vo);
        }
        __syncthreads();

        // ---- S = Q K^T (split, 3 terms) ----
        float sacc[8][4];
#pragma unroll
        for (int j = 0; j < 8; j++)
#pragma unroll
            for (int q = 0; q < 4; q++) sacc[j][q] = 0.f;
#pragma unroll
        for (int ks = 0; ks < 4; ks++) {
            int nr = (lane & 7) + ((lane >> 4) << 3);
            int kb = ks * 16 + (((lane >> 3) & 1) << 3);
#pragma unroll
            for (int np = 0; np < 4; np++) {
                uint32_t swo = sw128((uint32_t)((np * 16 + nr) * 128 + kb * 2));
                uint32_t bh4[4], bl4[4];
                LDSM_X4(bh4[0], bh4[1], bh4[2], bh4[3], sb + 16384 + swo);
                LDSM_X4(bl4[0], bl4[1], bl4[2], bl4[3], sb + 24576 + swo);
                mma16816(sacc[np * 2 + 0], qh[ks], bh4[0], bh4[1]);
                mma16816(sacc[np * 2 + 0], qh[ks], bl4[0], bl4[1]);
                mma16816(sacc[np * 2 + 0], ql[ks], bh4[0], bh4[1]);
                mma16816(sacc[np * 2 + 1], qh[ks], bh4[2], bh4[3]);
                mma16816(sacc[np * 2 + 1], qh[ks], bl4[2], bl4[3]);
                mma16816(sacc[np * 2 + 1], ql[ks], bh4[2], bh4[3]);
            }
        }

        // ---- scale + causal mask (diagonal tile only) ----
        const float scale = 0.125f;
        if (jt == it) {
            int r0 = wid * 16 + (lane >> 2);
#pragma unroll
            for (int nt = 0; nt < 8; nt++) {
                int c0 = nt * 8 + (lane & 3) * 2;
#pragma unroll
                for (int q = 0; q < 4; q++) {
                    int rr = r0 + ((q >> 1) << 3);
                    int cc = c0 + (q & 1);
                    sacc[nt][q] = (cc > rr) ? -1e30f : sacc[nt][q] * scale;
                }
            }
        } else {
#pragma unroll
            for (int nt = 0; nt < 8; nt++)
#pragma unroll
                for (int q = 0; q < 4; q++) sacc[nt][q] *= scale;
        }

        // ---- online softmax ----
        float tmax[2] = {-1e30f, -1e30f};
#pragma unroll
        for (int nt = 0; nt < 8; nt++) {
            tmax[0] = fmaxf(tmax[0], fmaxf(sacc[nt][0], sacc[nt][1]));
            tmax[1] = fmaxf(tmax[1], fmaxf(sacc[nt][2], sacc[nt][3]));
        }
#pragma unroll
        for (int o = 1; o <= 2; o <<= 1) {
            tmax[0] = fmaxf(tmax[0], __shfl_xor_sync(0xffffffffu, tmax[0], o));
            tmax[1] = fmaxf(tmax[1], __shfl_xor_sync(0xffffffffu, tmax[1], o));
        }
        float mnew0 = fmaxf(mrow[0], tmax[0]);
        float mnew1 = fmaxf(mrow[1], tmax[1]);
        float al0 = fast_exp(mrow[0] - mnew0);
        float al1 = fast_exp(mrow[1] - mnew1);
        mrow[0] = mnew0;
        mrow[1] = mnew1;
#pragma unroll
        for (int nt = 0; nt < 8; nt++) {
            oacc[nt][0] *= al0; oacc[nt][1] *= al0;
            oacc[nt][2] *= al1; oacc[nt][3] *= al1;
        }
        float tsum[2] = {0.f, 0.f};
#pragma unroll
        for (int nt = 0; nt < 8; nt++) {
            sacc[nt][0] = fast_exp(sacc[nt][0] - mnew0);
            sacc[nt][1] = fast_exp(sacc[nt][1] - mnew0);
            sacc[nt][2] = fast_exp(sacc[nt][2] - mnew1);
            sacc[nt][3] = fast_exp(sacc[nt][3] - mnew1);
            tsum[0] += sacc[nt][0] + sacc[nt][1];
            tsum[1] += sacc[nt][2] + sacc[nt][3];
        }
#pragma unroll
        for (int o = 1; o <= 2; o <<= 1) {
            tsum[0] += __shfl_xor_sync(0xffffffffu, tsum[0], o);
            tsum[1] += __shfl_xor_sync(0xffffffffu, tsum[1], o);
        }
        lrow[0] = lrow[0] * al0 + tsum[0];
        lrow[1] = lrow[1] * al1 + tsum[1];

        // ---- pack P to split-bf16 A fragments ----
        // a0 = (r, k0..1), a1 = (r+8, k0..1), a2 = (r, k8..9), a3 = (r+8, k8..9)
        uint32_t ph[4][4], pl[4][4];
#pragma unroll
        for (int ks2 = 0; ks2 < 4; ks2++) {
#pragma unroll
            for (int half = 0; half < 2; half++) {   // n8-tile within k16
                int nt = ks2 * 2 + half;
                __nv_bfloat16 h0, l0, h1, l1;
                split2(sacc[nt][0], h0, l0);
                split2(sacc[nt][1], h1, l1);
                __nv_bfloat162 hp = {h0, h1}, lp = {l0, l1};
                ph[ks2][half * 2 + 0] = *(uint32_t*)&hp;
                pl[ks2][half * 2 + 0] = *(uint32_t*)&lp;
                split2(sacc[nt][2], h0, l0);
                split2(sacc[nt][3], h1, l1);
                __nv_bfloat162 hp2 = {h0, h1}, lp2 = {l0, l1};
                ph[ks2][half * 2 + 1] = *(uint32_t*)&hp2;
                pl[ks2][half * 2 + 1] = *(uint32_t*)&lp2;
            }
        }

        // ---- O += P V (split, 3 terms); V^T fragments via trans ldmatrix ----
#pragma unroll
        for (int ks2 = 0; ks2 < 4; ks2++) {
            int tok = ks2 * 16 + (lane & 7) + (((lane >> 3) & 1) << 3);
#pragma unroll
            for (int np = 0; np < 4; np++) {
                int dh = np * 16 + ((lane >> 4) << 3);
                uint32_t swo = sw128((uint32_t)(tok * 128 + dh * 2));
                uint32_t vh4[4], vl4[4];
                LDSM_X4_T(vh4[0], vh4[1], vh4[2], vh4[3], sb + 32768 + swo);
                LDSM_X4_T(vl4[0], vl4[1], vl4[2], vl4[3], sb + 40960 + swo);
                mma16816(oacc[np * 2 + 0], ph[ks2], vh4[0], vh4[1]);
                mma16816(oacc[np * 2 + 0], ph[ks2], vl4[0], vl4[1]);
                mma16816(oacc[np * 2 + 0], pl[ks2], vh4[0], vh4[1]);
                mma16816(oacc[np * 2 + 1], ph[ks2], vh4[2], vh4[3]);
                mma16816(oacc[np * 2 + 1], ph[ks2], vl4[2], vl4[3]);
                mma16816(oacc[np * 2 + 1], pl[ks2], vh4[2], vh4[3]);
            }
        }
    }

    // ---- normalize + write split-bf16 attn-out, merged-head layout ----
    float inv0 = 1.0f / lrow[0];
    float inv1 = 1.0f / lrow[1];
    int qrow0 = it * 64 + wid * 16 + (lane >> 2);
    size_t base0 = (size_t)(b * SEQ + qrow0) * DMODEL + h * DHEAD;
    size_t base1 = (size_t)(b * SEQ + qrow0 + 8) * DMODEL + h * DHEAD;
#pragma unroll
    for (int nt = 0; nt < 8; nt++) {
        int col = nt * 8 + (lane & 3) * 2;
        __nv_bfloat162 h2, l2;
        split2(oacc[nt][0] * inv0, h2.x, l2.x);
        split2(oacc[nt][1] * inv0, h2.y, l2.y);
        *(__nv_bfloat162*)&ohi[base0 + col] = h2;
        *(__nv_bfloat162*)&olo[base0 + col] = l2;
        split2(oacc[nt][2] * inv1, h2.x, l2.x);
        split2(oacc[nt][3] * inv1, h2.y, l2.y);
        *(__nv_bfloat162*)&ohi[base1 + col] = h2;
        *(__nv_bfloat162*)&olo[base1 + col] = l2;
    }
}

// ---------------- orchestration ----------------
extern "C" void kernel_launch(void* const* d_in, const int* in_sizes, int n_in,
                              void* d_out, int out_size)
{
    const float* x_in   = (const float*)d_in[0];
    const float* qkv_w  = (const float*)d_in[1];
    const float* out_w  = (const float*)d_in[2];
    const float* ff_w1  = (const float*)d_in[3];
    const float* ff_w2  = (const float*)d_in[4];
    const float* attn_g = (const float*)d_in[5];
    const float* outln_g= (const float*)d_in[6];
    const float* ffn_g  = (const float*)d_in[7];
    const float* ffln_g = (const float*)d_in[8];
    const float* nin_g  = (const float*)d_in[9];
    const float* nout_g = (const float*)d_in[10];
    float* out = (float*)d_out;

    float *xbuf, *proj, *ff1;
    __nv_bfloat16 *ahi, *alo, *bhi, *blo, *qhi, *qlo;
    cudaGetSymbolAddress((void**)&xbuf,  g_xbuf);
    cudaGetSymbolAddress((void**)&proj,  g_proj);
    cudaGetSymbolAddress((void**)&ff1,   g_ff1);
    cudaGetSymbolAddress((void**)&ahi,   g_ahi);
    cudaGetSymbolAddress((void**)&alo,   g_alo);
    cudaGetSymbolAddress((void**)&bhi,   g_bhi);
    cudaGetSymbolAddress((void**)&blo,   g_blo);
    cudaGetSymbolAddress((void**)&qhi,   g_qkvhi);
    cudaGetSymbolAddress((void**)&qlo,   g_qkvlo);

    cudaFuncSetAttribute(gemm_mma_bf16x3, cudaFuncAttributeMaxDynamicSharedMemorySize, GSMEM);

    const int M = MROWS;
    ln_kernel<<<M, 256>>>(x_in, nin_g, nullptr, xbuf, DMODEL);

    for (int l = 0; l < NDEPTH; l++) {
        // ---- attention block ----
        ln_split<<<M, 256>>>(xbuf, attn_g + (size_t)l * DMODEL, ahi, alo, DMODEL);
        cvt_wt_t<<<dim3(3 * DMODEL / 32, DMODEL / 32), dim3(32, 8)>>>(
            qkv_w + (size_t)l * DMODEL * 3 * DMODEL, bhi, blo, DMODEL, 3 * DMODEL);
        gemm_mma_bf16x3<<<dim3(3 * DMODEL / GBN, M / GBM), 256, GSMEM>>>(
            ahi, alo, bhi, blo, nullptr, qhi, qlo, nullptr, M, 3 * DMODEL, DMODEL);

        flash_attn<<<dim3(16, BH), 128>>>(qhi, qlo, ahi, alo);

        cvt_wt_t<<<dim3(DMODEL / 32, DMODEL / 32), dim3(32, 8)>>>(
            out_w + (size_t)l * DMODEL * DMODEL, bhi, blo, DMODEL, DMODEL);
        gemm_mma_bf16x3<<<dim3(DMODEL / GBN, M / GBM), 256, GSMEM>>>(
            ahi, alo, bhi, blo, proj, nullptr, nullptr, nullptr, M, DMODEL, DMODEL);
        ln_kernel<<<M, 256>>>(proj, outln_g + (size_t)l * DMODEL, xbuf, xbuf, DMODEL);

        // ---- GEGLU feedforward ----
        ln_split<<<M, 256>>>(xbuf, ffn_g + (size_t)l * DMODEL, ahi, alo, DMODEL);
        cvt_wt_t<<<dim3(2 * FFI / 32, DMODEL / 32), dim3(32, 8)>>>(
            ff_w1 + (size_t)l * DMODEL * 2 * FFI, bhi, blo, DMODEL, 2 * FFI);
        gemm_mma_bf16x3<<<dim3(2 * FFI / GBN, M / GBM), 256, GSMEM>>>(
            ahi, alo, bhi, blo, ff1, nullptr, nullptr, nullptr, M, 2 * FFI, DMODEL);
        geglu_ln_split<<<M, 256>>>(ff1, ffln_g + (size_t)l * FFI, ahi, alo);
        cvt_wt_t<<<dim3(DMODEL / 32, FFI / 32), dim3(32, 8)>>>(
            ff_w2 + (size_t)l * FFI * DMODEL, bhi, blo, FFI, DMODEL);
        gemm_mma_bf16x3<<<dim3(DMODEL / GBN, M / GBM), 256, GSMEM>>>(
            ahi, alo, bhi, blo, xbuf, nullptr, nullptr, xbuf, M, DMODEL, FFI);
    }
    ln_kernel<<<M, 256>>>(xbuf, nout_g, nullptr, out, DMODEL);
}

// round 17
// speedup vs baseline: 1.3024x; 1.0148x over previous
#include <cuda_runtime.h>
#include <cuda_bf16.h>
#include <math.h>
#include <stdint.h>

typedef unsigned long long ull;

// ---------------- model dims ----------------
#define NDEPTH 6
#define DMODEL 1024
#define NHEADS 16
#define DHEAD  64
#define SEQ    1024
#define BATCH  4
#define MROWS  (BATCH*SEQ)        // 4096
#define FFI    4096               // FF_INNER
#define BH     (BATCH*NHEADS)     // 64

// ---------------- scratch (static device memory; no allocs allowed) ----------------
__device__ float g_xbuf [MROWS*DMODEL];
__device__ float g_proj [MROWS*DMODEL];
__device__ float g_ff1  [(size_t)MROWS*2*FFI];

__device__ __nv_bfloat16 g_ahi[(size_t)MROWS*FFI];       // GEMM A operand (split)
__device__ __nv_bfloat16 g_alo[(size_t)MROWS*FFI];
__device__ __nv_bfloat16 g_bhi[(size_t)(2*FFI)*DMODEL];  // weights [N,K] split
__device__ __nv_bfloat16 g_blo[(size_t)(2*FFI)*DMODEL];
__device__ __nv_bfloat16 g_qkvhi[(size_t)MROWS*3*DMODEL];
__device__ __nv_bfloat16 g_qkvlo[(size_t)MROWS*3*DMODEL];

// ---------------- helpers ----------------
__device__ __forceinline__ uint32_t smem_u32(const void* p) {
    uint32_t a;
    asm("{ .reg .u64 t; cvta.to.shared.u64 t, %1; cvt.u32.u64 %0, t; }" : "=r"(a) : "l"(p));
    return a;
}
__device__ __forceinline__ void mma16816(float* c, const uint32_t* a, uint32_t b0, uint32_t b1) {
    asm volatile(
        "mma.sync.aligned.m16n8k16.row.col.f32.bf16.bf16.f32 "
        "{%0,%1,%2,%3}, {%4,%5,%6,%7}, {%8,%9}, {%0,%1,%2,%3};"
        : "+f"(c[0]), "+f"(c[1]), "+f"(c[2]), "+f"(c[3])
        : "r"(a[0]), "r"(a[1]), "r"(a[2]), "r"(a[3]), "r"(b0), "r"(b1));
}
#define LDSM_X4(r0, r1, r2, r3, addr) \
    asm volatile("ldmatrix.sync.aligned.m8n8.x4.shared.b16 {%0,%1,%2,%3}, [%4];" \
                 : "=r"(r0), "=r"(r1), "=r"(r2), "=r"(r3) : "r"(addr))
#define LDSM_X4_T(r0, r1, r2, r3, addr) \
    asm volatile("ldmatrix.sync.aligned.m8n8.x4.trans.shared.b16 {%0,%1,%2,%3}, [%4];" \
                 : "=r"(r0), "=r"(r1), "=r"(r2), "=r"(r3) : "r"(addr))
#define CP_ASYNC16(saddr, gptr) \
    asm volatile("cp.async.cg.shared.global [%0], [%1], 16;" :: "r"(saddr), "l"(gptr))
__device__ __forceinline__ uint32_t sw128(uint32_t off) { return off ^ ((off >> 3) & 0x70u); }
__device__ __forceinline__ void split2(float v, __nv_bfloat16& h, __nv_bfloat16& l) {
    h = __float2bfloat16(v);
    l = __float2bfloat16(v - __bfloat162float(h));
}
// fast exp on the FMA pipe (no MUFU). Input clamped so (int) conversion is safe.
__device__ __forceinline__ float fast_exp(float x) {
    x = fmaxf(x, -87.0f);
    float t = x * 1.44269504088896340f;
    float r = rintf(t);
    float f = t - r;
    float p = 1.33335581e-3f;
    p = fmaf(p, f, 9.61812910e-3f);
    p = fmaf(p, f, 5.55041087e-2f);
    p = fmaf(p, f, 2.40226507e-1f);
    p = fmaf(p, f, 6.93147182e-1f);
    p = fmaf(p, f, 1.0f);
    int e = (int)r;
    if (e < -126) e = -126;
    float s = __int_as_float((uint32_t)(e + 127) << 23);
    return p * s;
}

// ---------------- fused split-bf16 tensor-core GEMM ----------------
// C = Ahi*Bhi + Ahi*Blo + Alo*Bhi computed in ONE K-pass.
// K32 chunks; each stage packs all four operands as 128B rows [hi 64B | lo 64B]
// (SW128 swizzle + LDSM addressing unchanged). 128x128 tile, 256 thr
// (8 warps, 32x64 warptile), 3-stage cp.async, 2 CTAs/SM.
#define GBM 128
#define GBN 128
#define GKC 32
#define NSTAGE 3
#define STAGE_BYTES 32768          // Apair 16KB + Bpair 16KB
#define GSMEM (NSTAGE*STAGE_BYTES + 1024)

__global__ void __launch_bounds__(256, 2) gemm_mma_bf16x3(
    const __nv_bfloat16* __restrict__ Ahi, const __nv_bfloat16* __restrict__ Alo,
    const __nv_bfloat16* __restrict__ Bhi, const __nv_bfloat16* __restrict__ Blo,
    float* __restrict__ C, __nv_bfloat16* __restrict__ Chi, __nv_bfloat16* __restrict__ Clo,
    const float* __restrict__ resid, int M, int N, int K)
{
    extern __shared__ char dsm[];
    const int tid = threadIdx.x;
    const int wid = tid >> 5, lane = tid & 31;
    const int bm = blockIdx.y * GBM, bn = blockIdx.x * GBN;
    const int m0 = (wid & 3) * 32;
    const int n0 = (wid >> 2) * 64;

    uint32_t raw = smem_u32(dsm);
    uint32_t base = (raw + 1023u) & ~1023u;

    const int NC = K / GKC;

    float acc[2][8][4];
#pragma unroll
    for (int i = 0; i < 2; i++)
#pragma unroll
        for (int j = 0; j < 8; j++)
#pragma unroll
            for (int q = 0; q < 4; q++) acc[i][j][q] = 0.f;

    // per-thread load coords: row lr (strided by 32), 16B column lq.
    // lq 0..3 -> hi half (bytes 0-63), lq 4..7 -> lo half (bytes 64-127).
    const int lr = tid >> 3, lq = tid & 7;
    const uint32_t lswo = sw128((uint32_t)(lr * 128 + lq * 16));
    const __nv_bfloat16* asrc = (lq < 4) ? Ahi : Alo;
    const __nv_bfloat16* bsrc = (lq < 4) ? Bhi : Blo;
    const int lqc = (lq & 3) * 8;   // element column within the K32 chunk

    auto issue = [&](int c) {
        int kc = c * GKC;
        uint32_t abase = base + (uint32_t)(c % NSTAGE) * STAGE_BYTES;
        uint32_t bbase = abase + 16384u;
        const __nv_bfloat16* ag = asrc + (size_t)(bm + lr) * K + kc + lqc;
        const __nv_bfloat16* bg = bsrc + (size_t)(bn + lr) * K + kc + lqc;
#pragma unroll
        for (int i = 0; i < 4; i++) {
            CP_ASYNC16(abase + lswo + i * 4096u, ag + (size_t)(i * 32) * K);
            CP_ASYNC16(bbase + lswo + i * 4096u, bg + (size_t)(i * 32) * K);
        }
        asm volatile("cp.async.commit_group;" ::: "memory");
    };

    issue(0);
    issue(1);

    for (int c = 0; c < NC; c++) {
        if (c + 2 < NC) {
            issue(c + 2);
            asm volatile("cp.async.wait_group 2;" ::: "memory");
        } else if (c + 1 < NC) {
            asm volatile("cp.async.wait_group 1;" ::: "memory");
        } else {
            asm volatile("cp.async.wait_group 0;" ::: "memory");
        }
        __syncthreads();

        uint32_t abase = base + (uint32_t)(c % NSTAGE) * STAGE_BYTES;
        uint32_t bbase = abase + 16384u;
#pragma unroll
        for (int ks = 0; ks < 2; ks++) {
            uint32_t ah[2][4], al[2][4];
#pragma unroll
            for (int mt = 0; mt < 2; mt++) {
                int row = m0 + mt * 16 + (lane & 15);
                int kb = ks * 16 + ((lane >> 4) << 3);          // 0..24 < 32
                uint32_t offh = (uint32_t)(row * 128 + kb * 2);
                LDSM_X4(ah[mt][0], ah[mt][1], ah[mt][2], ah[mt][3], abase + sw128(offh));
                LDSM_X4(al[mt][0], al[mt][1], al[mt][2], al[mt][3], abase + sw128(offh + 64u));
            }
#pragma unroll
            for (int np = 0; np < 4; np++) {
                int nr = n0 + np * 16 + (lane & 7) + ((lane >> 4) << 3);
                int kb = ks * 16 + (((lane >> 3) & 1) << 3);
                uint32_t offh = (uint32_t)(nr * 128 + kb * 2);
                uint32_t bh4[4], bl4[4];
                LDSM_X4(bh4[0], bh4[1], bh4[2], bh4[3], bbase + sw128(offh));
                LDSM_X4(bl4[0], bl4[1], bl4[2], bl4[3], bbase + sw128(offh + 64u));
#pragma unroll
                for (int mt = 0; mt < 2; mt++) {
                    mma16816(acc[mt][np * 2 + 0], ah[mt], bh4[0], bh4[1]);
                    mma16816(acc[mt][np * 2 + 0], ah[mt], bl4[0], bl4[1]);
                    mma16816(acc[mt][np * 2 + 0], al[mt], bh4[0], bh4[1]);
                    mma16816(acc[mt][np * 2 + 1], ah[mt], bh4[2], bh4[3]);
                    mma16816(acc[mt][np * 2 + 1], ah[mt], bl4[2], bl4[3]);
                    mma16816(acc[mt][np * 2 + 1], al[mt], bh4[2], bh4[3]);
                }
            }
        }
        __syncthreads();
    }

    // epilogue
#pragma unroll
    for (int mt = 0; mt < 2; mt++) {
        int row = bm + m0 + mt * 16 + (lane >> 2);
#pragma unroll
        for (int nt = 0; nt < 8; nt++) {
            int col = bn + n0 + nt * 8 + (lane & 3) * 2;
            size_t i0 = (size_t)row * N + col;
            size_t i1 = (size_t)(row + 8) * N + col;
            if (Chi) {
                __nv_bfloat162 h2, l2;
                split2(acc[mt][nt][0], h2.x, l2.x);
                split2(acc[mt][nt][1], h2.y, l2.y);
                *(__nv_bfloat162*)&Chi[i0] = h2;
                *(__nv_bfloat162*)&Clo[i0] = l2;
                split2(acc[mt][nt][2], h2.x, l2.x);
                split2(acc[mt][nt][3], h2.y, l2.y);
                *(__nv_bfloat162*)&Chi[i1] = h2;
                *(__nv_bfloat162*)&Clo[i1] = l2;
            } else if (resid) {
                float2 r0 = *(const float2*)&resid[i0];
                float2 r1 = *(const float2*)&resid[i1];
                *(float2*)&C[i0] = make_float2(acc[mt][nt][0] + r0.x, acc[mt][nt][1] + r0.y);
                *(float2*)&C[i1] = make_float2(acc[mt][nt][2] + r1.x, acc[mt][nt][3] + r1.y);
            } else {
                *(float2*)&C[i0] = make_float2(acc[mt][nt][0], acc[mt][nt][1]);
                *(float2*)&C[i1] = make_float2(acc[mt][nt][2], acc[mt][nt][3]);
            }
        }
    }
}

// ---------------- weights: W[K,N] row-major -> B[N,K] transposed split ----------------
__global__ void cvt_wt_t(const float* __restrict__ w, __nv_bfloat16* __restrict__ bhi,
                         __nv_bfloat16* __restrict__ blo, int K, int N)
{
    __shared__ float t[32][33];
    int k0 = blockIdx.y * 32, n0 = blockIdx.x * 32;
    int tx = threadIdx.x, ty = threadIdx.y;  // 32 x 8
    #pragma unroll
    for (int i = 0; i < 32; i += 8)
        t[ty + i][tx] = w[(size_t)(k0 + ty + i) * N + n0 + tx];
    __syncthreads();
    #pragma unroll
    for (int i = 0; i < 32; i += 8) {
        float v = t[tx][ty + i];
        __nv_bfloat16 h, l;
        split2(v, h, l);
        size_t o = (size_t)(n0 + ty + i) * K + k0 + tx;
        bhi[o] = h;
        blo[o] = l;
    }
}

// ---------------- LayerNorm helpers ----------------
__device__ __forceinline__ void red2(float& s, float& sq, int tid)
{
    __shared__ float sh[64];
    for (int o = 16; o; o >>= 1) { s += __shfl_xor_sync(0xffffffffu, s, o); sq += __shfl_xor_sync(0xffffffffu, sq, o); }
    int wid = tid >> 5, lid = tid & 31;
    if (lid == 0) { sh[wid] = s; sh[wid + 32] = sq; }
    __syncthreads();
    if (wid == 0) {
        float a = (lid < 8) ? sh[lid] : 0.f;
        float b = (lid < 8) ? sh[lid + 32] : 0.f;
        for (int o = 4; o; o >>= 1) { a += __shfl_xor_sync(0xffffffffu, a, o); b += __shfl_xor_sync(0xffffffffu, b, o); }
        if (lid == 0) { sh[0] = a; sh[1] = b; }
    }
    __syncthreads();
    s = sh[0];
    sq = sh[1];
}
__device__ __forceinline__ void ln_stats(const float* x, int D, int tid, float& mean, float& rstd)
{
    float s = 0.f, sq = 0.f;
    for (int c = tid; c < D; c += 256) { float v = x[c]; s += v; sq += v * v; }
    red2(s, sq, tid);
    mean = s / D;
    float var = sq / D - mean * mean;
    rstd = rsqrtf(var + 1e-5f);
}

__global__ void ln_kernel(const float* __restrict__ in, const float* __restrict__ g,
                          const float* __restrict__ res, float* __restrict__ out, int D)
{
    int row = blockIdx.x;
    const float* x = in + (size_t)row * D;
    float mean, rstd;
    ln_stats(x, D, threadIdx.x, mean, rstd);
    float* o = out + (size_t)row * D;
    const float* rr = res ? res + (size_t)row * D : nullptr;
    for (int c = threadIdx.x; c < D; c += 256) {
        float v = (x[c] - mean) * rstd * g[c];
        if (rr) v += rr[c];
        o[c] = v;
    }
}

__global__ void ln_split(const float* __restrict__ in, const float* __restrict__ g,
                         __nv_bfloat16* __restrict__ hi, __nv_bfloat16* __restrict__ lo, int D)
{
    int row = blockIdx.x;
    const float* x = in + (size_t)row * D;
    float mean, rstd;
    ln_stats(x, D, threadIdx.x, mean, rstd);
    for (int c = threadIdx.x; c < D; c += 256) {
        float v = (x[c] - mean) * rstd * g[c];
        __nv_bfloat16 h, l;
        split2(v, h, l);
        hi[(size_t)row * D + c] = h;
        lo[(size_t)row * D + c] = l;
    }
}

__global__ void geglu_ln_split(const float* __restrict__ ff1, const float* __restrict__ g,
                               __nv_bfloat16* __restrict__ hi, __nv_bfloat16* __restrict__ lo)
{
    int row = blockIdx.x;
    int tid = threadIdx.x;
    const float* arow = ff1 + (size_t)row * (2 * FFI);
    float val[FFI / 256];
    float s = 0.f, sq = 0.f;
#pragma unroll
    for (int k = 0; k < FFI / 256; k++) {
        int c = tid + k * 256;
        float a = arow[c];
        float gg = arow[FFI + c];
        float ge = 0.5f * gg * (1.0f + erff(gg * 0.70710678118654752f));
        float v = a * ge;
        val[k] = v;
        s += v;
        sq += v * v;
    }
    red2(s, sq, tid);
    float mean = s / FFI;
    float rstd = rsqrtf(sq / FFI - mean * mean + 1e-5f);
#pragma unroll
    for (int k = 0; k < FFI / 256; k++) {
        int c = tid + k * 256;
        float v = (val[k] - mean) * rstd * g[c];
        __nv_bfloat16 h, l;
        split2(v, h, l);
        hi[(size_t)row * FFI + c] = h;
        lo[(size_t)row * FFI + c] = l;
    }
}

// ---------------- fused flash attention (round-15 proven) ----------------
__global__ void __launch_bounds__(128) flash_attn(
    const __nv_bfloat16* __restrict__ qkvhi, const __nv_bfloat16* __restrict__ qkvlo,
    __nv_bfloat16* __restrict__ ohi, __nv_bfloat16* __restrict__ olo)
{
    __shared__ char sm[49152];
    uint32_t sb = smem_u32(sm);
    const int it = (int)gridDim.x - 1 - (int)blockIdx.x;   // big tiles first
    const int bh = blockIdx.y;
    const int b = bh >> 4, h = bh & 15;
    const int tid = threadIdx.x;
    const int wid = tid >> 5, lane = tid & 31;

    const size_t qrow = (size_t)(b * SEQ + it * 64) * (3 * DMODEL) + h * DHEAD;
#pragma unroll
    for (int i = 0; i < 4; i++) {
        int idx = tid + i * 128;
        int r = idx >> 3, q = idx & 7;
        uint32_t swo = sw128((uint32_t)(r * 128 + q * 16));
        size_t qo = qrow + (size_t)r * (3 * DMODEL) + q * 8;
        *(uint4*)(sm + swo)        = *(const uint4*)(qkvhi + qo);
        *(uint4*)(sm + 8192 + swo) = *(const uint4*)(qkvlo + qo);
    }
    __syncthreads();

    uint32_t qh[4][4], ql[4][4];
#pragma unroll
    for (int ks = 0; ks < 4; ks++) {
        int row = wid * 16 + (lane & 15);
        int kb = ks * 16 + ((lane >> 4) << 3);
        uint32_t swo = sw128((uint32_t)(row * 128 + kb * 2));
        LDSM_X4(qh[ks][0], qh[ks][1], qh[ks][2], qh[ks][3], sb + swo);
        LDSM_X4(ql[ks][0], ql[ks][1], ql[ks][2], ql[ks][3], sb + 8192 + swo);
    }

    float oacc[8][4];
#pragma unroll
    for (int j = 0; j < 8; j++)
#pragma unroll
        for (int q = 0; q < 4; q++) oacc[j][q] = 0.f;
    float mrow[2] = {-1e30f, -1e30f};
    float lrow[2] = {0.f, 0.f};

    const size_t kbase = (size_t)b * SEQ * (3 * DMODEL) + DMODEL + h * DHEAD;
    const size_t vbase = (size_t)b * SEQ * (3 * DMODEL) + 2 * DMODEL + h * DHEAD;

    for (int jt = 0; jt <= it; jt++) {
        __syncthreads();
#pragma unroll
        for (int i = 0; i < 4; i++) {
            int idx = tid + i * 128;
            int r = idx >> 3, q = idx & 7;
            uint32_t swo = sw128((uint32_t)(r * 128 + q * 16));
            size_t ko = kbase + (size_t)(jt * 64 + r) * (3 * DMODEL) + q * 8;
            size_t vo = vbase + (size_t)(jt * 64 + r) * (3 * DMODEL) + q * 8;
            *(uint4*)(sm + 16384 + swo) = *(const uint4*)(qkvhi + ko);
            *(uint4*)(sm + 24576 + swo) = *(const uint4*)(qkvlo + ko);
            *(uint4*)(sm + 32768 + swo) = *(const uint4*)(qkvhi + vo);
            *(uint4*)(sm + 40960 + swo) = *(const uint4*)(qkvlo + vo);
        }
        __syncthreads();

        float sacc[8][4];
#pragma unroll
        for (int j = 0; j < 8; j++)
#pragma unroll
            for (int q = 0; q < 4; q++) sacc[j][q] = 0.f;
#pragma unroll
        for (int ks = 0; ks < 4; ks++) {
            int nr = (lane & 7) + ((lane >> 4) << 3);
            int kb = ks * 16 + (((lane >> 3) & 1) << 3);
#pragma unroll
            for (int np = 0; np < 4; np++) {
                uint32_t swo = sw128((uint32_t)((np * 16 + nr) * 128 + kb * 2));
                uint32_t bh4[4], bl4[4];
                LDSM_X4(bh4[0], bh4[1], bh4[2], bh4[3], sb + 16384 + swo);
                LDSM_X4(bl4[0], bl4[1], bl4[2], bl4[3], sb + 24576 + swo);
                mma16816(sacc[np * 2 + 0], qh[ks], bh4[0], bh4[1]);
                mma16816(sacc[np * 2 + 0], qh[ks], bl4[0], bl4[1]);
                mma16816(sacc[np * 2 + 0], ql[ks], bh4[0], bh4[1]);
                mma16816(sacc[np * 2 + 1], qh[ks], bh4[2], bh4[3]);
                mma16816(sacc[np * 2 + 1], qh[ks], bl4[2], bl4[3]);
                mma16816(sacc[np * 2 + 1], ql[ks], bh4[2], bh4[3]);
            }
        }

        const float scale = 0.125f;
        if (jt == it) {
            int r0 = wid * 16 + (lane >> 2);
#pragma unroll
            for (int nt = 0; nt < 8; nt++) {
                int c0 = nt * 8 + (lane & 3) * 2;
#pragma unroll
                for (int q = 0; q < 4; q++) {
                    int rr = r0 + ((q >> 1) << 3);
                    int cc = c0 + (q & 1);
                    sacc[nt][q] = (cc > rr) ? -1e30f : sacc[nt][q] * scale;
                }
            }
        } else {
#pragma unroll
            for (int nt = 0; nt < 8; nt++)
#pragma unroll
                for (int q = 0; q < 4; q++) sacc[nt][q] *= scale;
        }

        float tmax[2] = {-1e30f, -1e30f};
#pragma unroll
        for (int nt = 0; nt < 8; nt++) {
            tmax[0] = fmaxf(tmax[0], fmaxf(sacc[nt][0], sacc[nt][1]));
            tmax[1] = fmaxf(tmax[1], fmaxf(sacc[nt][2], sacc[nt][3]));
        }
#pragma unroll
        for (int o = 1; o <= 2; o <<= 1) {
            tmax[0] = fmaxf(tmax[0], __shfl_xor_sync(0xffffffffu, tmax[0], o));
            tmax[1] = fmaxf(tmax[1], __shfl_xor_sync(0xffffffffu, tmax[1], o));
        }
        float mnew0 = fmaxf(mrow[0], tmax[0]);
        float mnew1 = fmaxf(mrow[1], tmax[1]);
        float al0 = fast_exp(mrow[0] - mnew0);
        float al1 = fast_exp(mrow[1] - mnew1);
        mrow[0] = mnew0;
        mrow[1] = mnew1;
#pragma unroll
        for (int nt = 0; nt < 8; nt++) {
            oacc[nt][0] *= al0; oacc[nt][1] *= al0;
            oacc[nt][2] *= al1; oacc[nt][3] *= al1;
        }
        float tsum[2] = {0.f, 0.f};
#pragma unroll
        for (int nt = 0; nt < 8; nt++) {
            sacc[nt][0] = fast_exp(sacc[nt][0] - mnew0);
            sacc[nt][1] = fast_exp(sacc[nt][1] - mnew0);
            sacc[nt][2] = fast_exp(sacc[nt][2] - mnew1);
            sacc[nt][3] = fast_exp(sacc[nt][3] - mnew1);
            tsum[0] += sacc[nt][0] + sacc[nt][1];
            tsum[1] += sacc[nt][2] + sacc[nt][3];
        }
#pragma unroll
        for (int o = 1; o <= 2; o <<= 1) {
            tsum[0] += __shfl_xor_sync(0xffffffffu, tsum[0], o);
            tsum[1] += __shfl_xor_sync(0xffffffffu, tsum[1], o);
        }
        lrow[0] = lrow[0] * al0 + tsum[0];
        lrow[1] = lrow[1] * al1 + tsum[1];

        uint32_t ph[4][4], pl[4][4];
#pragma unroll
        for (int ks2 = 0; ks2 < 4; ks2++) {
#pragma unroll
            for (int half = 0; half < 2; half++) {
                int nt = ks2 * 2 + half;
                __nv_bfloat16 h0, l0, h1, l1;
                split2(sacc[nt][0], h0, l0);
                split2(sacc[nt][1], h1, l1);
                __nv_bfloat162 hp = {h0, h1}, lp = {l0, l1};
                ph[ks2][half * 2 + 0] = *(uint32_t*)&hp;
                pl[ks2][half * 2 + 0] = *(uint32_t*)&lp;
                split2(sacc[nt][2], h0, l0);
                split2(sacc[nt][3], h1, l1);
                __nv_bfloat162 hp2 = {h0, h1}, lp2 = {l0, l1};
                ph[ks2][half * 2 + 1] = *(uint32_t*)&hp2;
                pl[ks2][half * 2 + 1] = *(uint32_t*)&lp2;
            }
        }

#pragma unroll
        for (int ks2 = 0; ks2 < 4; ks2++) {
            int tok = ks2 * 16 + (lane & 7) + (((lane >> 3) & 1) << 3);
#pragma unroll
            for (int np = 0; np < 4; np++) {
                int dh = np * 16 + ((lane >> 4) << 3);
                uint32_t swo = sw128((uint32_t)(tok * 128 + dh * 2));
                uint32_t vh4[4], vl4[4];
                LDSM_X4_T(vh4[0], vh4[1], vh4[2], vh4[3], sb + 32768 + swo);
                LDSM_X4_T(vl4[0], vl4[1], vl4[2], vl4[3], sb + 40960 + swo);
                mma16816(oacc[np * 2 + 0], ph[ks2], vh4[0], vh4[1]);
                mma16816(oacc[np * 2 + 0], ph[ks2], vl4[0], vl4[1]);
                mma16816(oacc[np * 2 + 0], pl[ks2], vh4[0], vh4[1]);
                mma16816(oacc[np * 2 + 1], ph[ks2], vh4[2], vh4[3]);
                mma16816(oacc[np * 2 + 1], ph[ks2], vl4[2], vl4[3]);
                mma16816(oacc[np * 2 + 1], pl[ks2], vh4[2], vh4[3]);
            }
        }
    }

    float inv0 = 1.0f / lrow[0];
    float inv1 = 1.0f / lrow[1];
    int qrow0 = it * 64 + wid * 16 + (lane >> 2);
    size_t base0 = (size_t)(b * SEQ + qrow0) * DMODEL + h * DHEAD;
    size_t base1 = (size_t)(b * SEQ + qrow0 + 8) * DMODEL + h * DHEAD;
#pragma unroll
    for (int nt = 0; nt < 8; nt++) {
        int col = nt * 8 + (lane & 3) * 2;
        __nv_bfloat162 h2, l2;
        split2(oacc[nt][0] * inv0, h2.x, l2.x);
        split2(oacc[nt][1] * inv0, h2.y, l2.y);
        *(__nv_bfloat162*)&ohi[base0 + col] = h2;
        *(__nv_bfloat162*)&olo[base0 + col] = l2;
        split2(oacc[nt][2] * inv1, h2.x, l2.x);
        split2(oacc[nt][3] * inv1, h2.y, l2.y);
        *(__nv_bfloat162*)&ohi[base1 + col] = h2;
        *(__nv_bfloat162*)&olo[base1 + col] = l2;
    }
}

// ---------------- orchestration ----------------
extern "C" void kernel_launch(void* const* d_in, const int* in_sizes, int n_in,
                              void* d_out, int out_size)
{
    const float* x_in   = (const float*)d_in[0];
    const float* qkv_w  = (const float*)d_in[1];
    const float* out_w  = (const float*)d_in[2];
    const float* ff_w1  = (const float*)d_in[3];
    const float* ff_w2  = (const float*)d_in[4];
    const float* attn_g = (const float*)d_in[5];
    const float* outln_g= (const float*)d_in[6];
    const float* ffn_g  = (const float*)d_in[7];
    const float* ffln_g = (const float*)d_in[8];
    const float* nin_g  = (const float*)d_in[9];
    const float* nout_g = (const float*)d_in[10];
    float* out = (float*)d_out;

    float *xbuf, *proj, *ff1;
    __nv_bfloat16 *ahi, *alo, *bhi, *blo, *qhi, *qlo;
    cudaGetSymbolAddress((void**)&xbuf,  g_xbuf);
    cudaGetSymbolAddress((void**)&proj,  g_proj);
    cudaGetSymbolAddress((void**)&ff1,   g_ff1);
    cudaGetSymbolAddress((void**)&ahi,   g_ahi);
    cudaGetSymbolAddress((void**)&alo,   g_alo);
    cudaGetSymbolAddress((void**)&bhi,   g_bhi);
    cudaGetSymbolAddress((void**)&blo,   g_blo);
    cudaGetSymbolAddress((void**)&qhi,   g_qkvhi);
    cudaGetSymbolAddress((void**)&qlo,   g_qkvlo);

    cudaFuncSetAttribute(gemm_mma_bf16x3, cudaFuncAttributeMaxDynamicSharedMemorySize, GSMEM);

    const int M = MROWS;
    ln_kernel<<<M, 256>>>(x_in, nin_g, nullptr, xbuf, DMODEL);

    for (int l = 0; l < NDEPTH; l++) {
        // ---- attention block ----
        ln_split<<<M, 256>>>(xbuf, attn_g + (size_t)l * DMODEL, ahi, alo, DMODEL);
        cvt_wt_t<<<dim3(3 * DMODEL / 32, DMODEL / 32), dim3(32, 8)>>>(
            qkv_w + (size_t)l * DMODEL * 3 * DMODEL, bhi, blo, DMODEL, 3 * DMODEL);
        gemm_mma_bf16x3<<<dim3(3 * DMODEL / GBN, M / GBM), 256, GSMEM>>>(
            ahi, alo, bhi, blo, nullptr, qhi, qlo, nullptr, M, 3 * DMODEL, DMODEL);

        flash_attn<<<dim3(16, BH), 128>>>(qhi, qlo, ahi, alo);

        cvt_wt_t<<<dim3(DMODEL / 32, DMODEL / 32), dim3(32, 8)>>>(
            out_w + (size_t)l * DMODEL * DMODEL, bhi, blo, DMODEL, DMODEL);
        gemm_mma_bf16x3<<<dim3(DMODEL / GBN, M / GBM), 256, GSMEM>>>(
            ahi, alo, bhi, blo, proj, nullptr, nullptr, nullptr, M, DMODEL, DMODEL);
        ln_kernel<<<M, 256>>>(proj, outln_g + (size_t)l * DMODEL, xbuf, xbuf, DMODEL);

        // ---- GEGLU feedforward ----
        ln_split<<<M, 256>>>(xbuf, ffn_g + (size_t)l * DMODEL, ahi, alo, DMODEL);
        cvt_wt_t<<<dim3(2 * FFI / 32, DMODEL / 32), dim3(32, 8)>>>(
            ff_w1 + (size_t)l * DMODEL * 2 * FFI, bhi, blo, DMODEL, 2 * FFI);
        gemm_mma_bf16x3<<<dim3(2 * FFI / GBN, M / GBM), 256, GSMEM>>>(
            ahi, alo, bhi, blo, ff1, nullptr, nullptr, nullptr, M, 2 * FFI, DMODEL);
        geglu_ln_split<<<M, 256>>>(ff1, ffln_g + (size_t)l * FFI, ahi, alo);
        cvt_wt_t<<<dim3(DMODEL / 32, FFI / 32), dim3(32, 8)>>>(
            ff_w2 + (size_t)l * FFI * DMODEL, bhi, blo, FFI, DMODEL);
        gemm_mma_bf16x3<<<dim3(DMODEL / GBN, M / GBM), 256, GSMEM>>>(
            ahi, alo, bhi, blo, xbuf, nullptr, nullptr, xbuf, M, DMODEL, FFI);
    }
    ln_kernel<<<M, 256>>>(xbuf, nout_g, nullptr, out, DMODEL);
}